// round 3
// baseline (speedup 1.0000x reference)
#include <cuda_runtime.h>
#include <math.h>

#define NBv 16
#define NLv 64
#define Vv  16384
#define Dv  256
#define TK  16
#define NIT 8
#define NROWS (NBv*NLv)   // 1024

// ---------------- scratch (static device memory; no allocs) ----------------
__device__ float  g_logits[NROWS][TK];
__device__ int    g_topidx[NROWS][TK];
__device__ int    g_map[NROWS];
__device__ int    g_samples[NIT][NROWS];
__device__ int    g_gidx[NIT][NROWS];
__device__ float  g_HW[NBv][NLv*Dv];
__device__ float  g_NE[NIT*NBv][NLv*Dv];   // 8 MB
__device__ float  g_scores[NIT][NBv];
__device__ int    g_best[NROWS];

// ---------------- threefry2x32 (JAX 20-round), host+device ----------------
__host__ __device__ inline void tf2x32(unsigned k0, unsigned k1, unsigned& x0, unsigned& x1){
  unsigned ks2 = k0 ^ k1 ^ 0x1BD11BDAu;
#define ROTL32(x,d) (((x)<<(d))|((x)>>(32-(d))))
#define TFRND(r) { x0 += x1; x1 = ROTL32(x1,(r)); x1 ^= x0; }
  x0 += k0; x1 += k1;
  TFRND(13) TFRND(15) TFRND(26) TFRND(6)
  x0 += k1; x1 += ks2 + 1u;
  TFRND(17) TFRND(29) TFRND(16) TFRND(24)
  x0 += ks2; x1 += k0 + 2u;
  TFRND(13) TFRND(15) TFRND(26) TFRND(6)
  x0 += k0; x1 += k1 + 3u;
  TFRND(17) TFRND(29) TFRND(16) TFRND(24)
  x0 += k1; x1 += ks2 + 4u;
  TFRND(13) TFRND(15) TFRND(26) TFRND(6)
  x0 += ks2; x1 += k0 + 5u;
#undef TFRND
#undef ROTL32
}

struct Keys { unsigned a[2*NIT]; };

// ---------------- kernel 1: per-row top-16 + argmax + logits ----------------
__global__ __launch_bounds__(256) void k_topk(const float* __restrict__ probas,
                                              const int* __restrict__ mask){
  int row = blockIdx.x;
  const float* p = probas + (size_t)row * Vv;
  int t = threadIdx.x;
  unsigned long long loc[TK];
#pragma unroll
  for (int i=0;i<TK;i++) loc[i]=0ull;
  unsigned long long mn=0ull; int mnp=0;
  for (int v=t; v<Vv; v+=256){
    unsigned fb = __float_as_uint(__ldg(&p[v]));   // probas > 0 -> monotonic bits
    unsigned long long key = ((unsigned long long)fb<<32) | (unsigned)(~v);
    if (key > mn){
      loc[mnp]=key;
      mn = loc[0]; mnp=0;
#pragma unroll
      for (int i=1;i<TK;i++) if (loc[i] < mn){ mn=loc[i]; mnp=i; }
    }
  }
  __shared__ unsigned long long pool[256*TK];
  __shared__ unsigned long long sred[256];
  __shared__ int sidx[256];
  __shared__ unsigned long long res[TK];
#pragma unroll
  for (int i=0;i<TK;i++) pool[t*TK+i]=loc[i];
  __syncthreads();
  for (int r=0;r<TK;r++){
    unsigned long long mx=0ull; int ms=t*TK;
#pragma unroll
    for (int s=0;s<TK;s++){ unsigned long long k2=pool[t*TK+s]; if (k2>mx){mx=k2;ms=t*TK+s;} }
    sred[t]=mx; sidx[t]=ms;
    __syncthreads();
    for (int s=128;s>0;s>>=1){
      if (t<s){ if (sred[t+s]>sred[t]){ sred[t]=sred[t+s]; sidx[t]=sidx[t+s]; } }
      __syncthreads();
    }
    if (t==0){ res[r]=sred[0]; pool[sidx[0]]=0ull; }
    __syncthreads();
  }
  if (t<TK){
    unsigned long long key = res[t];
    int idx = (int)(~(unsigned)key);
    float val = __uint_as_float((unsigned)(key>>32));
    g_topidx[row][t]=idx;
    g_logits[row][t] = mask[row] ? logf(val) : 0.0f;   // masked rows: topk_vals->1.0 -> log 0
    if (t==0) g_map[row]=idx;
  }
}

// ---------------- kernel 2: gumbel-categorical sampling ----------------
// Partitionable threefry (JAX >= 0.4.36 default):
//   bits[e] = x0 ^ x1 of threefry2x32(key, counter=(0, e)),  e = row*16 + j
// gumbel computed in f32 exactly like XLA (libdevice logf).
__global__ __launch_bounds__(1024) void k_sample(const int* __restrict__ mask,
                                                 const int* __restrict__ bvocab, Keys keys){
  int k = blockIdx.x;                // iteration index
  int row = threadIdx.x;             // 0..1023 = b*64+l
  unsigned k0=keys.a[2*k], k1=keys.a[2*k+1];
  float best=-INFINITY; int arg=0;
  unsigned base = (unsigned)(row*TK);
#pragma unroll
  for (int j=0;j<TK;j++){
    unsigned x0 = 0u, x1 = base+(unsigned)j;
    tf2x32(k0,k1,x0,x1);
    unsigned bits = x0 ^ x1;
    unsigned ub = (bits>>9) | 0x3f800000u;
    float f = __uint_as_float(ub) - 1.0f;
    float u = (f>0.f)? f : 1.17549435e-38f;        // uniform(minval=tiny,maxval=1)
    float gf = -logf(-logf(u));                    // gumbel, f32 like XLA
    float s = gf + g_logits[row][j];
    if (s>best){best=s;arg=j;}                     // first max wins (jnp.argmax)
  }
  int s = g_topidx[row][arg];
  int ll = row&63;
  bool oh = mask[row] && (ll==63 || mask[row+1]==0);  // l == sLens-1 (prefix mask)
  if (oh) s = g_map[row];
  g_samples[k][row]=s;
  g_gidx[k][row]=bvocab[s];
}

// ---------------- kernel 3: HW[b] = (h_d*mask) @ W1[256:512] ----------------
__global__ __launch_bounds__(256) void k_hw(const float* __restrict__ h_d,
                                            const int* __restrict__ mask,
                                            const float* __restrict__ W1){
  int blk = blockIdx.x; int b = blk>>2; int cc = (blk&3)*64;
  int t = threadIdx.x; int ty=t>>4, tx=t&15;
  __shared__ float As[32][65];
  __shared__ float Bs[32][64];
  __shared__ float mf[64];
  if (t<64) mf[t] = (float)mask[b*64+t];
  __syncthreads();
  float acc[4][4];
#pragma unroll
  for (int i=0;i<4;i++)
#pragma unroll
    for (int j=0;j<4;j++) acc[i][j]=0.f;
  for (int k0=0;k0<Dv;k0+=32){
#pragma unroll
    for (int i=0;i<8;i++){
      int e=t+i*256; int r=e>>5, kk=e&31;
      As[kk][r] = h_d[((size_t)b*64+r)*Dv + k0+kk] * mf[r];
    }
#pragma unroll
    for (int i=0;i<8;i++){
      int e=t+i*256; int kk=e>>6, c=e&63;
      Bs[kk][c] = W1[(size_t)(Dv + k0+kk)*Dv + cc + c];
    }
    __syncthreads();
#pragma unroll
    for (int kk=0;kk<32;kk++){
      float a0=As[kk][ty],a1=As[kk][ty+16],a2=As[kk][ty+32],a3=As[kk][ty+48];
      float w0=Bs[kk][tx],w1=Bs[kk][tx+16],w2=Bs[kk][tx+32],w3=Bs[kk][tx+48];
      acc[0][0]+=a0*w0; acc[0][1]+=a0*w1; acc[0][2]+=a0*w2; acc[0][3]+=a0*w3;
      acc[1][0]+=a1*w0; acc[1][1]+=a1*w1; acc[1][2]+=a1*w2; acc[1][3]+=a1*w3;
      acc[2][0]+=a2*w0; acc[2][1]+=a2*w1; acc[2][2]+=a2*w2; acc[2][3]+=a2*w3;
      acc[3][0]+=a3*w0; acc[3][1]+=a3*w1; acc[3][2]+=a3*w2; acc[3][3]+=a3*w3;
    }
    __syncthreads();
  }
#pragma unroll
  for (int ri=0;ri<4;ri++)
#pragma unroll
    for (int ci=0;ci<4;ci++)
      g_HW[b][(ty+16*ri)*Dv + cc + tx+16*ci] = acc[ri][ci];
}

// ---------------- kernel 4: NE = relu(E@W1[0:256] + HW + b1) ----------------
__global__ __launch_bounds__(256) void k_ne(const float* __restrict__ emb,
                                            const int* __restrict__ mask,
                                            const float* __restrict__ W1,
                                            const float* __restrict__ b1){
  int blk=blockIdx.x;
  int task=blk>>2; int cc=(blk&3)*64;
  int k=task>>4, b=task&15;
  int t=threadIdx.x; int ty=t>>4, tx=t&15;
  __shared__ float As[32][65];
  __shared__ float Bs[32][64];
  __shared__ int gid[64]; __shared__ float mf[64];
  if (t<64){ gid[t]=g_gidx[k][b*64+t]; mf[t]=(float)mask[b*64+t]; }
  __syncthreads();
  float acc[4][4];
#pragma unroll
  for (int i=0;i<4;i++)
#pragma unroll
    for (int j=0;j<4;j++) acc[i][j]=0.f;
  for (int k0=0;k0<Dv;k0+=32){
#pragma unroll
    for (int i=0;i<8;i++){
      int e=t+i*256; int r=e>>5, kk=e&31;
      As[kk][r] = emb[(size_t)gid[r]*Dv + k0+kk]*mf[r];
    }
#pragma unroll
    for (int i=0;i<8;i++){
      int e=t+i*256; int kk=e>>6, c=e&63;
      Bs[kk][c] = W1[(size_t)(k0+kk)*Dv + cc+c];
    }
    __syncthreads();
#pragma unroll
    for (int kk=0;kk<32;kk++){
      float a0=As[kk][ty],a1=As[kk][ty+16],a2=As[kk][ty+32],a3=As[kk][ty+48];
      float w0=Bs[kk][tx],w1=Bs[kk][tx+16],w2=Bs[kk][tx+32],w3=Bs[kk][tx+48];
      acc[0][0]+=a0*w0; acc[0][1]+=a0*w1; acc[0][2]+=a0*w2; acc[0][3]+=a0*w3;
      acc[1][0]+=a1*w0; acc[1][1]+=a1*w1; acc[1][2]+=a1*w2; acc[1][3]+=a1*w3;
      acc[2][0]+=a2*w0; acc[2][1]+=a2*w1; acc[2][2]+=a2*w2; acc[2][3]+=a2*w3;
      acc[3][0]+=a3*w0; acc[3][1]+=a3*w1; acc[3][2]+=a3*w2; acc[3][3]+=a3*w3;
    }
    __syncthreads();
  }
#pragma unroll
  for (int ri=0;ri<4;ri++)
#pragma unroll
    for (int ci=0;ci<4;ci++){
      int r=ty+16*ri, c=cc+tx+16*ci;
      float v = acc[ri][ci] + g_HW[b][r*Dv+c] + b1[c];
      g_NE[task][(size_t)r*Dv+c] = fmaxf(v,0.f);
    }
}

// ---------------- kernel 5: Gram + masked-identity + LU det ----------------
__global__ __launch_bounds__(256) void k_det(const int* __restrict__ mask){
  int task = blockIdx.x;          // k*16+b
  int b = task & 15;
  int t = threadIdx.x;
  int ti = t>>4, tj = t&15;
  __shared__ float As[64][33];
  __shared__ float M[64][65];
  __shared__ int vld[64];
  if (t<64) vld[t]=mask[b*64+t];
  float acc[4][4];
#pragma unroll
  for (int i=0;i<4;i++)
#pragma unroll
    for (int j=0;j<4;j++) acc[i][j]=0.f;
  const float* NE = g_NE[task];
  for (int k0=0;k0<Dv;k0+=32){
#pragma unroll
    for (int i=0;i<8;i++){
      int e=t+i*256; int r=e>>5, kk=e&31;
      As[r][kk] = NE[(size_t)r*Dv + k0+kk];
    }
    __syncthreads();
#pragma unroll
    for (int kk=0;kk<32;kk++){
      float a0=As[ti][kk],a1=As[ti+16][kk],a2=As[ti+32][kk],a3=As[ti+48][kk];
      float c0=As[tj][kk],c1=As[tj+16][kk],c2=As[tj+32][kk],c3=As[tj+48][kk];
      acc[0][0]+=a0*c0; acc[0][1]+=a0*c1; acc[0][2]+=a0*c2; acc[0][3]+=a0*c3;
      acc[1][0]+=a1*c0; acc[1][1]+=a1*c1; acc[1][2]+=a1*c2; acc[1][3]+=a1*c3;
      acc[2][0]+=a2*c0; acc[2][1]+=a2*c1; acc[2][2]+=a2*c2; acc[2][3]+=a2*c3;
      acc[3][0]+=a3*c0; acc[3][1]+=a3*c1; acc[3][2]+=a3*c2; acc[3][3]+=a3*c3;
    }
    __syncthreads();
  }
#pragma unroll
  for (int ri=0;ri<4;ri++)
#pragma unroll
    for (int ci=0;ci<4;ci++){
      int r=ti+16*ri, c=tj+16*ci;
      float v = acc[ri][ci];
      if (!(vld[r] && vld[c])) v = (r==c)?1.f:0.f;   // where(m2d,K,eye)
      M[r][c]=v;
    }
  __syncthreads();
  // LU with partial pivoting
  __shared__ float red[64]; __shared__ int redi[64]; __shared__ float fct[64];
  __shared__ double sdet;
  if (t==0) sdet=1.0;
  for (int i=0;i<64;i++){
    if (t<64){ red[t] = (t>=i)? fabsf(M[t][i]) : -1.f; redi[t]=t; }
    __syncthreads();
    for (int s=32;s>0;s>>=1){
      if (t<s){ if (red[t+s]>red[t]){red[t]=red[t+s];redi[t]=redi[t+s];} }
      __syncthreads();
    }
    int p = redi[0];
    if (p != i){
      for (int c=i+t;c<64;c+=256){ float tmp=M[i][c]; M[i][c]=M[p][c]; M[p][c]=tmp; }
    }
    __syncthreads();
    float piv = M[i][i];
    if (t==0){ sdet *= (double)piv; if (p!=i) sdet = -sdet; }
    if (t>i && t<64) fct[t] = M[t][i]/piv;
    __syncthreads();
    int n = 63-i;
    for (int e=t;e<n*n;e+=256){
      int r=i+1+e/n, c=i+1+e%n;
      M[r][c] -= fct[r]*M[i][c];
    }
    __syncthreads();
  }
  if (t==0){ g_scores[task>>4][b] = (float)sdet; }
}

// ---------------- kernel 6: scan-carry (improved/count/stopped) ----------------
__global__ __launch_bounds__(1024) void k_carry(float* __restrict__ out_scores){
  int t=threadIdx.x;
  __shared__ float ms[NBv];
  __shared__ int sbest[NROWS];
  __shared__ int imp[NBv];
  __shared__ int s_ost, s_count, s_stop;
  if (t<NBv) ms[t]=-INFINITY;
  sbest[t]=g_map[t];
  if (t==0){s_count=0;s_stop=0;s_ost=0;}
  __syncthreads();
  for (int k=0;k<NIT;k++){
    if (t<NBv) imp[t] = (g_scores[k][t] > ms[t])?1:0;
    __syncthreads();
    if (t==0){
      int a=0; for (int bb=0;bb<NBv;bb++) a|=imp[bb];
      s_ost = s_stop;                               // upd uses OLD stopped
      s_count = a?0:(s_count+1);
      if ((!a) && s_count>=2) s_stop=1;
    }
    __syncthreads();
    if (t<NBv && imp[t] && !s_ost) ms[t]=g_scores[k][t];
    if (imp[t>>6] && !s_ost) sbest[t]=g_samples[k][t];
    __syncthreads();
  }
  g_best[t]=sbest[t];
  if (t<NBv) out_scores[t]=ms[t];
}

// ---------------- kernel 7: diverse_proba scatter-renormalize ----------------
__global__ __launch_bounds__(256) void k_out(const float* __restrict__ probas,
                                             const int* __restrict__ mask,
                                             float* __restrict__ out){
  int row=blockIdx.x;
  const float* p = probas + (size_t)row*Vv;
  float* o = out + (size_t)row*Vv;
  int t=threadIdx.x;
  int bv = g_best[row];
  float s=0.f;
  for (int v=t;v<Vv;v+=256){
    float x = __ldg(&p[v]);
    s += x * ((v==bv)?0.8f:0.2f);
  }
  __shared__ float sr[256];
  sr[t]=s; __syncthreads();
  for (int w=128;w>0;w>>=1){ if(t<w) sr[t]+=sr[t+w]; __syncthreads(); }
  float nm = mask[row] ? sr[0] : 1e-10f;
  float inv = 1.0f/nm;
  for (int v=t;v<Vv;v+=256){
    float x = __ldg(&p[v]);
    o[v] = x * ((v==bv)?0.8f:0.2f) * inv;
  }
}

// ---------------- launch ----------------
extern "C" void kernel_launch(void* const* d_in, const int* in_sizes, int n_in,
                              void* d_out, int out_size){
  const float* probas = (const float*)d_in[0];
  const float* h_d    = (const float*)d_in[1];
  const int*   mask   = (const int*)d_in[2];
  const int*   bvocab = (const int*)d_in[3];
  const float* emb    = (const float*)d_in[4];
  const float* W1     = (const float*)d_in[5];
  const float* b1     = (const float*)d_in[6];
  float* out = (float*)d_out;
  (void)in_sizes; (void)n_in;

  // jax.random.split(jax.random.key(42), 8), partitionable/foldlike:
  // key_k = threefry2x32((0,42), (0,k)) -> (x0, x1)
  Keys keys;
  for (int k=0;k<NIT;k++){
    unsigned x0=0u, x1=(unsigned)k;
    tf2x32(0u,42u,x0,x1);
    keys.a[2*k]=x0; keys.a[2*k+1]=x1;
  }

  k_topk  <<<NROWS,256>>>(probas, mask);
  k_sample<<<NIT, 1024>>>(mask, bvocab, keys);
  k_hw    <<<64,   256>>>(h_d, mask, W1);
  k_ne    <<<512,  256>>>(emb, mask, W1, b1);
  k_det   <<<128,  256>>>(mask);
  k_carry <<<1,   1024>>>(out + (size_t)out_size - NBv);
  k_out   <<<NROWS,256>>>(probas, mask, out);
}

// round 4
// speedup vs baseline: 1.2175x; 1.2175x over previous
#include <cuda_runtime.h>
#include <math.h>

#define NBv 16
#define NLv 64
#define Vv  16384
#define Dv  256
#define TK  16
#define NIT 8
#define NROWS (NBv*NLv)   // 1024

// ---------------- scratch (static device memory; no allocs) ----------------
__device__ float  g_logits[NROWS][TK];
__device__ int    g_topidx[NROWS][TK];
__device__ int    g_map[NROWS];
__device__ int    g_samples[NIT][NROWS];
__device__ int    g_gidx[NIT][NROWS];
__device__ float  g_HW[NBv][NLv*Dv];
__device__ float  g_NE[NIT*NBv][NLv*Dv];   // 8 MB
__device__ float  g_scores[NIT][NBv];
__device__ int    g_best[NROWS];

// ---------------- threefry2x32 (JAX 20-round), host+device ----------------
__host__ __device__ inline void tf2x32(unsigned k0, unsigned k1, unsigned& x0, unsigned& x1){
  unsigned ks2 = k0 ^ k1 ^ 0x1BD11BDAu;
#define ROTL32(x,d) (((x)<<(d))|((x)>>(32-(d))))
#define TFRND(r) { x0 += x1; x1 = ROTL32(x1,(r)); x1 ^= x0; }
  x0 += k0; x1 += k1;
  TFRND(13) TFRND(15) TFRND(26) TFRND(6)
  x0 += k1; x1 += ks2 + 1u;
  TFRND(17) TFRND(29) TFRND(16) TFRND(24)
  x0 += ks2; x1 += k0 + 2u;
  TFRND(13) TFRND(15) TFRND(26) TFRND(6)
  x0 += k0; x1 += k1 + 3u;
  TFRND(17) TFRND(29) TFRND(16) TFRND(24)
  x0 += k1; x1 += ks2 + 4u;
  TFRND(13) TFRND(15) TFRND(26) TFRND(6)
  x0 += ks2; x1 += k0 + 5u;
#undef TFRND
#undef ROTL32
}

struct Keys { unsigned a[2*NIT]; };

// ---------------- kernel 1: per-row top-16 + argmax + logits ----------------
__global__ __launch_bounds__(256) void k_topk(const float* __restrict__ probas,
                                              const int* __restrict__ mask){
  int row = blockIdx.x;
  const float4* p4 = (const float4*)(probas + (size_t)row * Vv);
  int t = threadIdx.x;
  unsigned long long loc[TK];
#pragma unroll
  for (int i=0;i<TK;i++) loc[i]=0ull;
  unsigned long long mn=0ull; int mnp=0;
#pragma unroll 4
  for (int i=0;i<16;i++){
    int v4 = i*256 + t;
    float4 x = __ldg(&p4[v4]);
    float xs[4] = {x.x, x.y, x.z, x.w};
#pragma unroll
    for (int q=0;q<4;q++){
      int v = v4*4+q;
      unsigned fb = __float_as_uint(xs[q]);   // probas > 0 -> monotonic bits
      unsigned long long key = ((unsigned long long)fb<<32) | (unsigned)(~v);
      if (key > mn){
        loc[mnp]=key;
        mn = loc[0]; mnp=0;
#pragma unroll
        for (int u=1;u<TK;u++) if (loc[u] < mn){ mn=loc[u]; mnp=u; }
      }
    }
  }
  __shared__ unsigned long long pool[256*TK];
  __shared__ unsigned long long sred[256];
  __shared__ int sidx[256];
  __shared__ unsigned long long res[TK];
#pragma unroll
  for (int i=0;i<TK;i++) pool[t*TK+i]=loc[i];
  __syncthreads();
  for (int r=0;r<TK;r++){
    unsigned long long mx=0ull; int ms=t*TK;
#pragma unroll
    for (int s=0;s<TK;s++){ unsigned long long k2=pool[t*TK+s]; if (k2>mx){mx=k2;ms=t*TK+s;} }
    sred[t]=mx; sidx[t]=ms;
    __syncthreads();
    for (int s=128;s>0;s>>=1){
      if (t<s){ if (sred[t+s]>sred[t]){ sred[t]=sred[t+s]; sidx[t]=sidx[t+s]; } }
      __syncthreads();
    }
    if (t==0){ res[r]=sred[0]; pool[sidx[0]]=0ull; }
    __syncthreads();
  }
  if (t<TK){
    unsigned long long key = res[t];
    int idx = (int)(~(unsigned)key);
    float val = __uint_as_float((unsigned)(key>>32));
    g_topidx[row][t]=idx;
    g_logits[row][t] = mask[row] ? logf(val) : 0.0f;   // masked rows: topk_vals->1.0 -> log 0
    if (t==0) g_map[row]=idx;
  }
}

// ---------------- kernel 2: gumbel-categorical sampling ----------------
// Partitionable threefry: bits[e] = x0^x1 of threefry2x32(key, (0,e)), e=row*16+j.
// One thread per draw; 16-lane shfl tournament = jnp.argmax first-max semantics.
__global__ __launch_bounds__(256) void k_sample(const int* __restrict__ mask,
                                                 const int* __restrict__ bvocab, Keys keys){
  int flat = blockIdx.x*256 + threadIdx.x;   // 0..131071
  int j   = flat & 15;
  int row = (flat>>4) & (NROWS-1);
  int k   = flat >> 14;
  unsigned k0=keys.a[2*k], k1=keys.a[2*k+1];
  unsigned x0=0u, x1=(unsigned)(row*TK + j);
  tf2x32(k0,k1,x0,x1);
  unsigned bits = x0 ^ x1;
  unsigned ub = (bits>>9) | 0x3f800000u;
  float f = __uint_as_float(ub) - 1.0f;
  float u = (f>0.f)? f : 1.17549435e-38f;     // uniform(minval=tiny,maxval=1)
  float s = -logf(-logf(u)) + g_logits[row][j];
  int arg = j;
#pragma unroll
  for (int w=1; w<16; w<<=1){
    float os = __shfl_xor_sync(0xffffffffu, s, w);
    int   oa = __shfl_xor_sync(0xffffffffu, arg, w);
    if (os>s || (os==s && oa<arg)){ s=os; arg=oa; }
  }
  if (j==0){
    int smp = g_topidx[row][arg];
    int ll = row&63;
    bool oh = mask[row] && (ll==63 || mask[row+1]==0);  // l == sLens-1 (prefix mask)
    if (oh) smp = g_map[row];
    g_samples[k][row]=smp;
    g_gidx[k][row]=bvocab[smp];
  }
}

// ---------------- kernel 3: HW[b] = (h_d*mask) @ W1[256:512] ----------------
__global__ __launch_bounds__(256) void k_hw(const float* __restrict__ h_d,
                                            const int* __restrict__ mask,
                                            const float* __restrict__ W1){
  int blk = blockIdx.x; int b = blk>>2; int cc = (blk&3)*64;
  int t = threadIdx.x; int ty=t>>4, tx=t&15;
  __shared__ float As[32][65];
  __shared__ float Bs[32][64];
  __shared__ float mf[64];
  if (t<64) mf[t] = (float)mask[b*64+t];
  __syncthreads();
  float acc[4][4];
#pragma unroll
  for (int i=0;i<4;i++)
#pragma unroll
    for (int j=0;j<4;j++) acc[i][j]=0.f;
  for (int k0=0;k0<Dv;k0+=32){
#pragma unroll
    for (int i=0;i<8;i++){
      int e=t+i*256; int r=e>>5, kk=e&31;
      As[kk][r] = h_d[((size_t)b*64+r)*Dv + k0+kk] * mf[r];
    }
#pragma unroll
    for (int i=0;i<8;i++){
      int e=t+i*256; int kk=e>>6, c=e&63;
      Bs[kk][c] = W1[(size_t)(Dv + k0+kk)*Dv + cc + c];
    }
    __syncthreads();
#pragma unroll
    for (int kk=0;kk<32;kk++){
      float a0=As[kk][ty],a1=As[kk][ty+16],a2=As[kk][ty+32],a3=As[kk][ty+48];
      float w0=Bs[kk][tx],w1=Bs[kk][tx+16],w2=Bs[kk][tx+32],w3=Bs[kk][tx+48];
      acc[0][0]+=a0*w0; acc[0][1]+=a0*w1; acc[0][2]+=a0*w2; acc[0][3]+=a0*w3;
      acc[1][0]+=a1*w0; acc[1][1]+=a1*w1; acc[1][2]+=a1*w2; acc[1][3]+=a1*w3;
      acc[2][0]+=a2*w0; acc[2][1]+=a2*w1; acc[2][2]+=a2*w2; acc[2][3]+=a2*w3;
      acc[3][0]+=a3*w0; acc[3][1]+=a3*w1; acc[3][2]+=a3*w2; acc[3][3]+=a3*w3;
    }
    __syncthreads();
  }
#pragma unroll
  for (int ri=0;ri<4;ri++)
#pragma unroll
    for (int ci=0;ci<4;ci++)
      g_HW[b][(ty+16*ri)*Dv + cc + tx+16*ci] = acc[ri][ci];
}

// ---------------- kernel 4: NE = relu(E@W1[0:256] + HW + b1) ----------------
// 64x128 tile per block, 4x8 register blocking (32 FMA / 12 LDS per kk).
__global__ __launch_bounds__(256) void k_ne(const float* __restrict__ emb,
                                            const int* __restrict__ mask,
                                            const float* __restrict__ W1,
                                            const float* __restrict__ b1){
  int blk=blockIdx.x;
  int task=blk>>1; int cc=(blk&1)*128;
  int k=task>>4, b=task&15;
  int t=threadIdx.x; int ty=t>>4, tx=t&15;
  __shared__ float As[32][65];
  __shared__ float Bs[32][132];
  __shared__ int gid[64]; __shared__ float mf[64];
  if (t<64){ gid[t]=g_gidx[k][b*64+t]; mf[t]=(float)mask[b*64+t]; }
  __syncthreads();
  float acc[4][8];
#pragma unroll
  for (int i=0;i<4;i++)
#pragma unroll
    for (int j=0;j<8;j++) acc[i][j]=0.f;
  for (int k0=0;k0<Dv;k0+=32){
#pragma unroll
    for (int i=0;i<8;i++){
      int e=t+i*256; int r=e>>5, kk=e&31;
      As[kk][r] = emb[(size_t)gid[r]*Dv + k0+kk]*mf[r];
    }
#pragma unroll
    for (int i=0;i<16;i++){
      int e=t+i*256; int kk=e>>7, c=e&127;
      Bs[kk][c] = W1[(size_t)(k0+kk)*Dv + cc+c];
    }
    __syncthreads();
#pragma unroll
    for (int kk=0;kk<32;kk++){
      float a[4], w[8];
#pragma unroll
      for (int ri=0;ri<4;ri++) a[ri]=As[kk][ty+16*ri];
#pragma unroll
      for (int ci=0;ci<8;ci++) w[ci]=Bs[kk][tx+16*ci];
#pragma unroll
      for (int ri=0;ri<4;ri++)
#pragma unroll
        for (int ci=0;ci<8;ci++) acc[ri][ci] += a[ri]*w[ci];
    }
    __syncthreads();
  }
#pragma unroll
  for (int ri=0;ri<4;ri++)
#pragma unroll
    for (int ci=0;ci<8;ci++){
      int r=ty+16*ri, c=cc+tx+16*ci;
      float v = acc[ri][ci] + g_HW[b][r*Dv+c] + b1[c];
      g_NE[task][(size_t)r*Dv+c] = fmaxf(v,0.f);
    }
}

// ---------------- kernel 5: Gram + masked-identity + LU det ----------------
__global__ __launch_bounds__(256) void k_det(const int* __restrict__ mask){
  int task = blockIdx.x;          // k*16+b
  int b = task & 15;
  int t = threadIdx.x;
  int ti = t>>4, tj = t&15;
  __shared__ float As[64][33];
  __shared__ float M[64][65];
  __shared__ int vld[64];
  if (t<64) vld[t]=mask[b*64+t];
  float acc[4][4];
#pragma unroll
  for (int i=0;i<4;i++)
#pragma unroll
    for (int j=0;j<4;j++) acc[i][j]=0.f;
  const float* NE = g_NE[task];
  for (int k0=0;k0<Dv;k0+=32){
#pragma unroll
    for (int i=0;i<8;i++){
      int e=t+i*256; int r=e>>5, kk=e&31;
      As[r][kk] = NE[(size_t)r*Dv + k0+kk];
    }
    __syncthreads();
#pragma unroll
    for (int kk=0;kk<32;kk++){
      float a0=As[ti][kk],a1=As[ti+16][kk],a2=As[ti+32][kk],a3=As[ti+48][kk];
      float c0=As[tj][kk],c1=As[tj+16][kk],c2=As[tj+32][kk],c3=As[tj+48][kk];
      acc[0][0]+=a0*c0; acc[0][1]+=a0*c1; acc[0][2]+=a0*c2; acc[0][3]+=a0*c3;
      acc[1][0]+=a1*c0; acc[1][1]+=a1*c1; acc[1][2]+=a1*c2; acc[1][3]+=a1*c3;
      acc[2][0]+=a2*c0; acc[2][1]+=a2*c1; acc[2][2]+=a2*c2; acc[2][3]+=a2*c3;
      acc[3][0]+=a3*c0; acc[3][1]+=a3*c1; acc[3][2]+=a3*c2; acc[3][3]+=a3*c3;
    }
    __syncthreads();
  }
#pragma unroll
  for (int ri=0;ri<4;ri++)
#pragma unroll
    for (int ci=0;ci<4;ci++){
      int r=ti+16*ri, c=tj+16*ci;
      float v = acc[ri][ci];
      if (!(vld[r] && vld[c])) v = (r==c)?1.f:0.f;   // where(m2d,K,eye)
      M[r][c]=v;
    }
  __syncthreads();
  // LU with partial pivoting
  __shared__ float red[64]; __shared__ int redi[64]; __shared__ float fct[64];
  __shared__ double sdet;
  if (t==0) sdet=1.0;
  for (int i=0;i<64;i++){
    if (t<64){ red[t] = (t>=i)? fabsf(M[t][i]) : -1.f; redi[t]=t; }
    __syncthreads();
    for (int s=32;s>0;s>>=1){
      if (t<s){ if (red[t+s]>red[t]){red[t]=red[t+s];redi[t]=redi[t+s];} }
      __syncthreads();
    }
    int p = redi[0];
    if (p != i){
      for (int c=i+t;c<64;c+=256){ float tmp=M[i][c]; M[i][c]=M[p][c]; M[p][c]=tmp; }
    }
    __syncthreads();
    float piv = M[i][i];
    if (t==0){ sdet *= (double)piv; if (p!=i) sdet = -sdet; }
    if (t>i && t<64) fct[t] = M[t][i]/piv;
    __syncthreads();
    int n = 63-i;
    for (int e=t;e<n*n;e+=256){
      int r=i+1+e/n, c=i+1+e%n;
      M[r][c] -= fct[r]*M[i][c];
    }
    __syncthreads();
  }
  if (t==0){ g_scores[task>>4][b] = (float)sdet; }
}

// ---------------- kernel 6: scan-carry (improved/count/stopped) ----------------
__global__ __launch_bounds__(1024) void k_carry(float* __restrict__ out_scores){
  int t=threadIdx.x;
  __shared__ float ms[NBv];
  __shared__ int sbest[NROWS];
  __shared__ int imp[NBv];
  __shared__ int s_ost, s_count, s_stop;
  if (t<NBv) ms[t]=-INFINITY;
  sbest[t]=g_map[t];
  if (t==0){s_count=0;s_stop=0;s_ost=0;}
  __syncthreads();
  for (int k=0;k<NIT;k++){
    if (t<NBv) imp[t] = (g_scores[k][t] > ms[t])?1:0;
    __syncthreads();
    if (t==0){
      int a=0; for (int bb=0;bb<NBv;bb++) a|=imp[bb];
      s_ost = s_stop;                               // upd uses OLD stopped
      s_count = a?0:(s_count+1);
      if ((!a) && s_count>=2) s_stop=1;
    }
    __syncthreads();
    if (t<NBv && imp[t] && !s_ost) ms[t]=g_scores[k][t];
    if (imp[t>>6] && !s_ost) sbest[t]=g_samples[k][t];
    __syncthreads();
  }
  g_best[t]=sbest[t];
  if (t<NBv) out_scores[t]=ms[t];
}

// ---------------- kernel 7: diverse_proba scatter-renormalize ----------------
__global__ __launch_bounds__(256) void k_out(const float* __restrict__ probas,
                                             const int* __restrict__ mask,
                                             float* __restrict__ out){
  int row=blockIdx.x;
  const float4* p4 = (const float4*)(probas + (size_t)row*Vv);
  float4* o4 = (float4*)(out + (size_t)row*Vv);
  int t=threadIdx.x;
  int bv = g_best[row];
  int bv4 = bv>>2, bvl = bv&3;
  float s=0.f;
#pragma unroll 4
  for (int i=0;i<16;i++){
    int v4=i*256+t;
    float4 x = __ldg(&p4[v4]);
    float w0=(v4==bv4&&bvl==0)?0.8f:0.2f, w1=(v4==bv4&&bvl==1)?0.8f:0.2f;
    float w2=(v4==bv4&&bvl==2)?0.8f:0.2f, w3=(v4==bv4&&bvl==3)?0.8f:0.2f;
    s += x.x*w0 + x.y*w1 + x.z*w2 + x.w*w3;
  }
  __shared__ float sr[256];
  sr[t]=s; __syncthreads();
  for (int w=128;w>0;w>>=1){ if(t<w) sr[t]+=sr[t+w]; __syncthreads(); }
  float nm = mask[row] ? sr[0] : 1e-10f;
  float inv = 1.0f/nm;
#pragma unroll 4
  for (int i=0;i<16;i++){
    int v4=i*256+t;
    float4 x = __ldg(&p4[v4]);
    float w0=(v4==bv4&&bvl==0)?0.8f:0.2f, w1=(v4==bv4&&bvl==1)?0.8f:0.2f;
    float w2=(v4==bv4&&bvl==2)?0.8f:0.2f, w3=(v4==bv4&&bvl==3)?0.8f:0.2f;
    float4 y; y.x=x.x*w0*inv; y.y=x.y*w1*inv; y.z=x.z*w2*inv; y.w=x.w*w3*inv;
    o4[v4]=y;
  }
}

// ---------------- launch ----------------
extern "C" void kernel_launch(void* const* d_in, const int* in_sizes, int n_in,
                              void* d_out, int out_size){
  const float* probas = (const float*)d_in[0];
  const float* h_d    = (const float*)d_in[1];
  const int*   mask   = (const int*)d_in[2];
  const int*   bvocab = (const int*)d_in[3];
  const float* emb    = (const float*)d_in[4];
  const float* W1     = (const float*)d_in[5];
  const float* b1     = (const float*)d_in[6];
  float* out = (float*)d_out;
  (void)in_sizes; (void)n_in;

  // jax.random.split(jax.random.key(42), 8), partitionable/foldlike:
  // key_k = threefry2x32((0,42), (0,k)) -> (x0, x1)
  Keys keys;
  for (int k=0;k<NIT;k++){
    unsigned x0=0u, x1=(unsigned)k;
    tf2x32(0u,42u,x0,x1);
    keys.a[2*k]=x0; keys.a[2*k+1]=x1;
  }

  k_topk  <<<NROWS,256>>>(probas, mask);
  k_sample<<<512,  256>>>(mask, bvocab, keys);
  k_hw    <<<64,   256>>>(h_d, mask, W1);
  k_ne    <<<256,  256>>>(emb, mask, W1, b1);
  k_det   <<<128,  256>>>(mask);
  k_carry <<<1,   1024>>>(out + (size_t)out_size - NBv);
  k_out   <<<NROWS,256>>>(probas, mask, out);
}

// round 5
// speedup vs baseline: 1.7314x; 1.4220x over previous
#include <cuda_runtime.h>
#include <math.h>

#define NBv 16
#define NLv 64
#define Vv  16384
#define Dv  256
#define TK  16
#define NIT 8
#define NROWS (NBv*NLv)   // 1024

// ---------------- scratch (static device memory; no allocs) ----------------
__device__ float  g_logits[NROWS][TK];
__device__ int    g_topidx[NROWS][TK];
__device__ int    g_map[NROWS];
__device__ int    g_samples[NIT][NROWS];
__device__ int    g_gidx[NIT][NROWS];
__device__ float  g_HW[NBv][NLv*Dv];
__device__ float  g_NE[NIT*NBv][NLv*Dv];   // 8 MB
__device__ float  g_scores[NIT][NBv];
__device__ int    g_best[NROWS];

// ---------------- threefry2x32 (JAX 20-round), host+device ----------------
__host__ __device__ inline void tf2x32(unsigned k0, unsigned k1, unsigned& x0, unsigned& x1){
  unsigned ks2 = k0 ^ k1 ^ 0x1BD11BDAu;
#define ROTL32(x,d) (((x)<<(d))|((x)>>(32-(d))))
#define TFRND(r) { x0 += x1; x1 = ROTL32(x1,(r)); x1 ^= x0; }
  x0 += k0; x1 += k1;
  TFRND(13) TFRND(15) TFRND(26) TFRND(6)
  x0 += k1; x1 += ks2 + 1u;
  TFRND(17) TFRND(29) TFRND(16) TFRND(24)
  x0 += ks2; x1 += k0 + 2u;
  TFRND(13) TFRND(15) TFRND(26) TFRND(6)
  x0 += k0; x1 += k1 + 3u;
  TFRND(17) TFRND(29) TFRND(16) TFRND(24)
  x0 += k1; x1 += ks2 + 4u;
  TFRND(13) TFRND(15) TFRND(26) TFRND(6)
  x0 += ks2; x1 += k0 + 5u;
#undef TFRND
#undef ROTL32
}

struct Keys { unsigned a[2*NIT]; };

// ---------------- kernel 1: per-row top-16 + argmax + logits ----------------
// Per-thread top-16 in registers (static indexing only), warp-shfl tournament
// merge (no shared-memory scans -> no bank conflicts), 1 block barrier.
__global__ __launch_bounds__(256) void k_topk(const float* __restrict__ probas,
                                              const int* __restrict__ mask){
  int row = blockIdx.x;
  const float4* p4 = (const float4*)(probas + (size_t)row * Vv);
  int t = threadIdx.x;
  int lane = t & 31, warp = t >> 5;

  unsigned long long v[TK];           // ascending: v[0] = current min of kept
#pragma unroll
  for (int i=0;i<TK;i++) v[i]=0ull;

#pragma unroll 4
  for (int i=0;i<16;i++){
    int v4 = i*256 + t;
    float4 x = __ldg(&p4[v4]);
    float xs[4] = {x.x, x.y, x.z, x.w};
#pragma unroll
    for (int q=0;q<4;q++){
      int vidx = v4*4+q;
      unsigned fb = __float_as_uint(xs[q]);    // probas>0 -> bits monotonic
      unsigned long long key = ((unsigned long long)fb<<32) | (unsigned)(~vidx);
      if (key > v[0]){
        v[0]=key;
        // one bubble pass restores sortedness (only v[0] was out of place)
#pragma unroll
        for (int u=0;u<TK-1;u++){
          unsigned long long a=v[u], b=v[u+1];
          bool sw = a>b;
          v[u]   = sw? b : a;
          v[u+1] = sw? a : b;
        }
      }
    }
  }
  // reverse to descending
  unsigned long long w[TK];
#pragma unroll
  for (int i=0;i<TK;i++) w[i]=v[TK-1-i];

  // warp tournament: extract 16 largest of the warp's 512 candidates
  __shared__ unsigned long long sw8[8][TK];
  unsigned long long mine = 0ull;
  for (int r=0;r<TK;r++){
    unsigned long long bh = w[0]; int bl = lane;
#pragma unroll
    for (int d=16; d>0; d>>=1){
      unsigned long long oh = __shfl_xor_sync(0xffffffffu, bh, d);
      int ol = __shfl_xor_sync(0xffffffffu, bl, d);
      if (oh > bh){ bh=oh; bl=ol; }
    }
    if (lane==bl){
#pragma unroll
      for (int u=0;u<TK-1;u++) w[u]=w[u+1];
      w[TK-1]=0ull;
    }
    if (lane==r) mine = bh;
  }
  if (lane<TK) sw8[warp][lane] = mine;     // descending per warp
  __syncthreads();

  if (warp==0){
    unsigned long long c[4];
    int wsrc = lane>>2, base=(lane&3)*4;
#pragma unroll
    for (int j=0;j<4;j++) c[j]=sw8[wsrc][base+j];   // descending per lane
    unsigned long long res = 0ull;
    for (int r=0;r<TK;r++){
      unsigned long long bh=c[0]; int bl=lane;
#pragma unroll
      for (int d=16; d>0; d>>=1){
        unsigned long long oh = __shfl_xor_sync(0xffffffffu, bh, d);
        int ol = __shfl_xor_sync(0xffffffffu, bl, d);
        if (oh > bh){ bh=oh; bl=ol; }
      }
      if (lane==bl){ c[0]=c[1]; c[1]=c[2]; c[2]=c[3]; c[3]=0ull; }
      if (lane==r) res = bh;
    }
    if (lane<TK){
      int idx = (int)(~(unsigned)res);
      float val = __uint_as_float((unsigned)(res>>32));
      g_topidx[row][lane]=idx;
      g_logits[row][lane] = mask[row] ? logf(val) : 0.0f;  // masked: log(1)=0
      if (lane==0) g_map[row]=idx;
    }
  }
}

// ---------------- kernel 2: gumbel-categorical sampling ----------------
// Partitionable threefry: bits[e] = x0^x1 of threefry2x32(key, (0,e)), e=row*16+j.
__global__ __launch_bounds__(256) void k_sample(const int* __restrict__ mask,
                                                 const int* __restrict__ bvocab, Keys keys){
  int flat = blockIdx.x*256 + threadIdx.x;   // 0..131071
  int j   = flat & 15;
  int row = (flat>>4) & (NROWS-1);
  int k   = flat >> 14;
  unsigned k0=keys.a[2*k], k1=keys.a[2*k+1];
  unsigned x0=0u, x1=(unsigned)(row*TK + j);
  tf2x32(k0,k1,x0,x1);
  unsigned bits = x0 ^ x1;
  unsigned ub = (bits>>9) | 0x3f800000u;
  float f = __uint_as_float(ub) - 1.0f;
  float u = (f>0.f)? f : 1.17549435e-38f;     // uniform(minval=tiny,maxval=1)
  float s = -logf(-logf(u)) + g_logits[row][j];
  int arg = j;
#pragma unroll
  for (int w=1; w<16; w<<=1){
    float os = __shfl_xor_sync(0xffffffffu, s, w);
    int   oa = __shfl_xor_sync(0xffffffffu, arg, w);
    if (os>s || (os==s && oa<arg)){ s=os; arg=oa; }
  }
  if (j==0){
    int smp = g_topidx[row][arg];
    int ll = row&63;
    bool oh = mask[row] && (ll==63 || mask[row+1]==0);  // l == sLens-1 (prefix mask)
    if (oh) smp = g_map[row];
    g_samples[k][row]=smp;
    g_gidx[k][row]=bvocab[smp];
  }
}

// ---------------- kernel 3: HW[b] = (h_d*mask) @ W1[256:512] ----------------
__global__ __launch_bounds__(256) void k_hw(const float* __restrict__ h_d,
                                            const int* __restrict__ mask,
                                            const float* __restrict__ W1){
  int blk = blockIdx.x; int b = blk>>2; int cc = (blk&3)*64;
  int t = threadIdx.x; int ty=t>>4, tx=t&15;
  __shared__ float As[32][65];
  __shared__ float Bs[32][64];
  __shared__ float mf[64];
  if (t<64) mf[t] = (float)mask[b*64+t];
  __syncthreads();
  float acc[4][4];
#pragma unroll
  for (int i=0;i<4;i++)
#pragma unroll
    for (int j=0;j<4;j++) acc[i][j]=0.f;
  for (int k0=0;k0<Dv;k0+=32){
#pragma unroll
    for (int i=0;i<8;i++){
      int e=t+i*256; int r=e>>5, kk=e&31;
      As[kk][r] = h_d[((size_t)b*64+r)*Dv + k0+kk] * mf[r];
    }
#pragma unroll
    for (int i=0;i<8;i++){
      int e=t+i*256; int kk=e>>6, c=e&63;
      Bs[kk][c] = W1[(size_t)(Dv + k0+kk)*Dv + cc + c];
    }
    __syncthreads();
#pragma unroll
    for (int kk=0;kk<32;kk++){
      float a0=As[kk][ty],a1=As[kk][ty+16],a2=As[kk][ty+32],a3=As[kk][ty+48];
      float w0=Bs[kk][tx],w1=Bs[kk][tx+16],w2=Bs[kk][tx+32],w3=Bs[kk][tx+48];
      acc[0][0]+=a0*w0; acc[0][1]+=a0*w1; acc[0][2]+=a0*w2; acc[0][3]+=a0*w3;
      acc[1][0]+=a1*w0; acc[1][1]+=a1*w1; acc[1][2]+=a1*w2; acc[1][3]+=a1*w3;
      acc[2][0]+=a2*w0; acc[2][1]+=a2*w1; acc[2][2]+=a2*w2; acc[2][3]+=a2*w3;
      acc[3][0]+=a3*w0; acc[3][1]+=a3*w1; acc[3][2]+=a3*w2; acc[3][3]+=a3*w3;
    }
    __syncthreads();
  }
#pragma unroll
  for (int ri=0;ri<4;ri++)
#pragma unroll
    for (int ci=0;ci<4;ci++)
      g_HW[b][(ty+16*ri)*Dv + cc + tx+16*ci] = acc[ri][ci];
}

// ---------------- kernel 4: NE = relu(E@W1[0:256] + HW + b1) ----------------
// 64x128 tile per block, 4x8 register blocking.
__global__ __launch_bounds__(256) void k_ne(const float* __restrict__ emb,
                                            const int* __restrict__ mask,
                                            const float* __restrict__ W1,
                                            const float* __restrict__ b1){
  int blk=blockIdx.x;
  int task=blk>>1; int cc=(blk&1)*128;
  int k=task>>4, b=task&15;
  int t=threadIdx.x; int ty=t>>4, tx=t&15;
  __shared__ __align__(16) float As[32][65];
  __shared__ __align__(16) float Bs[32][132];
  __shared__ int gid[64]; __shared__ float mf[64];
  if (t<64){ gid[t]=g_gidx[k][b*64+t]; mf[t]=(float)mask[b*64+t]; }
  __syncthreads();
  float acc[4][8];
#pragma unroll
  for (int i=0;i<4;i++)
#pragma unroll
    for (int j=0;j<8;j++) acc[i][j]=0.f;
  for (int k0=0;k0<Dv;k0+=32){
#pragma unroll
    for (int i=0;i<8;i++){
      int e=t+i*256; int r=e>>5, kk=e&31;
      As[kk][r] = emb[(size_t)gid[r]*Dv + k0+kk]*mf[r];
    }
    // B tile via float4: 32 rows x 128 cols = 1024 float4, 4 per thread
#pragma unroll
    for (int i=0;i<4;i++){
      int e=t+i*256; int kk=e>>5, c4=e&31;
      float4 wv = *(const float4*)&W1[(size_t)(k0+kk)*Dv + cc + c4*4];
      *(float4*)&Bs[kk][c4*4] = wv;
    }
    __syncthreads();
#pragma unroll
    for (int kk=0;kk<32;kk++){
      float a[4], w[8];
#pragma unroll
      for (int ri=0;ri<4;ri++) a[ri]=As[kk][ty+16*ri];
#pragma unroll
      for (int ci=0;ci<8;ci++) w[ci]=Bs[kk][tx+16*ci];
#pragma unroll
      for (int ri=0;ri<4;ri++)
#pragma unroll
        for (int ci=0;ci<8;ci++) acc[ri][ci] += a[ri]*w[ci];
    }
    __syncthreads();
  }
#pragma unroll
  for (int ri=0;ri<4;ri++)
#pragma unroll
    for (int ci=0;ci<8;ci++){
      int r=ty+16*ri, c=cc+tx+16*ci;
      float v = acc[ri][ci] + g_HW[b][r*Dv+c] + b1[c];
      g_NE[task][(size_t)r*Dv+c] = fmaxf(v,0.f);
    }
}

// ---------------- kernel 5: Gram + masked-identity + LU det ----------------
__global__ __launch_bounds__(256) void k_det(const int* __restrict__ mask){
  int task = blockIdx.x;          // k*16+b
  int b = task & 15;
  int t = threadIdx.x;
  int lane = t & 31, warp = t >> 5;
  int ti = t>>4, tj = t&15;
  __shared__ float As[64][33];
  __shared__ float M[64][65];
  __shared__ int vld[64];
  if (t<64) vld[t]=mask[b*64+t];
  float acc[4][4];
#pragma unroll
  for (int i=0;i<4;i++)
#pragma unroll
    for (int j=0;j<4;j++) acc[i][j]=0.f;
  const float* NE = g_NE[task];
  for (int k0=0;k0<Dv;k0+=32){
#pragma unroll
    for (int i=0;i<8;i++){
      int e=t+i*256; int r=e>>5, kk=e&31;
      As[r][kk] = NE[(size_t)r*Dv + k0+kk];
    }
    __syncthreads();
#pragma unroll
    for (int kk=0;kk<32;kk++){
      float a0=As[ti][kk],a1=As[ti+16][kk],a2=As[ti+32][kk],a3=As[ti+48][kk];
      float c0=As[tj][kk],c1=As[tj+16][kk],c2=As[tj+32][kk],c3=As[tj+48][kk];
      acc[0][0]+=a0*c0; acc[0][1]+=a0*c1; acc[0][2]+=a0*c2; acc[0][3]+=a0*c3;
      acc[1][0]+=a1*c0; acc[1][1]+=a1*c1; acc[1][2]+=a1*c2; acc[1][3]+=a1*c3;
      acc[2][0]+=a2*c0; acc[2][1]+=a2*c1; acc[2][2]+=a2*c2; acc[2][3]+=a2*c3;
      acc[3][0]+=a3*c0; acc[3][1]+=a3*c1; acc[3][2]+=a3*c2; acc[3][3]+=a3*c3;
    }
    __syncthreads();
  }
#pragma unroll
  for (int ri=0;ri<4;ri++)
#pragma unroll
    for (int ci=0;ci<4;ci++){
      int r=ti+16*ri, c=tj+16*ci;
      float v = acc[ri][ci];
      if (!(vld[r] && vld[c])) v = (r==c)?1.f:0.f;   // where(m2d,K,eye)
      M[r][c]=v;
    }

  // LU with partial pivoting: warp-0 pivot search, 3 barriers/iter, no div/mod
  __shared__ float fct[64];
  __shared__ int sp;
  __shared__ double sdet;
  if (t==0) sdet=1.0;
  __syncthreads();
  for (int i=0;i<64;i++){
    if (warp==0){
      unsigned long long k1=0ull, k2=0ull;
      if (lane>=i)
        k1 = ((unsigned long long)__float_as_uint(fabsf(M[lane][i]))<<32) | (unsigned)(63-lane);
      if (lane+32>=i)
        k2 = ((unsigned long long)__float_as_uint(fabsf(M[lane+32][i]))<<32) | (unsigned)(63-(lane+32));
      unsigned long long bk = (k1>k2)? k1:k2;
#pragma unroll
      for (int d=16; d>0; d>>=1){
        unsigned long long ok = __shfl_xor_sync(0xffffffffu, bk, d);
        if (ok>bk) bk=ok;
      }
      if (lane==0) sp = 63-(int)(bk & 0xffffffffu);
    }
    __syncthreads();
    int p = sp;
    if (t<64 && p!=i){
      float a=M[i][t], c=M[p][t];
      M[i][t]=c; M[p][t]=a;
    }
    __syncthreads();
    float piv = M[i][i];
    if (t==0){ double d=(double)piv; sdet *= (p!=i)? -d : d; }
    if (t<64 && t>i) fct[t]=M[t][i]/piv;
    __syncthreads();
    int tr = t>>6;          // 0..3
    int tc = t&63;
    if (tc>i){
      float mi = M[i][tc];
      for (int r=i+1+tr; r<64; r+=4)
        M[r][tc] -= fct[r]*mi;
    }
    __syncthreads();
  }
  if (t==0) g_scores[task>>4][b] = (float)sdet;
}

// ---------------- kernel 6: scan-carry (improved/count/stopped) ----------------
__global__ __launch_bounds__(1024) void k_carry(float* __restrict__ out_scores){
  int t=threadIdx.x;
  __shared__ float ms[NBv];
  __shared__ int sbest[NROWS];
  __shared__ int imp[NBv];
  __shared__ int s_ost, s_count, s_stop;
  if (t<NBv) ms[t]=-INFINITY;
  sbest[t]=g_map[t];
  if (t==0){s_count=0;s_stop=0;s_ost=0;}
  __syncthreads();
  for (int k=0;k<NIT;k++){
    if (t<NBv) imp[t] = (g_scores[k][t] > ms[t])?1:0;
    __syncthreads();
    if (t==0){
      int a=0; for (int bb=0;bb<NBv;bb++) a|=imp[bb];
      s_ost = s_stop;                               // upd uses OLD stopped
      s_count = a?0:(s_count+1);
      if ((!a) && s_count>=2) s_stop=1;
    }
    __syncthreads();
    if (t<NBv && imp[t] && !s_ost) ms[t]=g_scores[k][t];
    if (imp[t>>6] && !s_ost) sbest[t]=g_samples[k][t];
    __syncthreads();
  }
  g_best[t]=sbest[t];
  if (t<NBv) out_scores[t]=ms[t];
}

// ---------------- kernel 7: diverse_proba scatter-renormalize ----------------
__global__ __launch_bounds__(256) void k_out(const float* __restrict__ probas,
                                             const int* __restrict__ mask,
                                             float* __restrict__ out){
  int row=blockIdx.x;
  const float4* p4 = (const float4*)(probas + (size_t)row*Vv);
  float4* o4 = (float4*)(out + (size_t)row*Vv);
  int t=threadIdx.x;
  int bv = g_best[row];
  int bv4 = bv>>2, bvl = bv&3;
  float s=0.f;
#pragma unroll 4
  for (int i=0;i<16;i++){
    int v4=i*256+t;
    float4 x = __ldg(&p4[v4]);
    float w0=(v4==bv4&&bvl==0)?0.8f:0.2f, w1=(v4==bv4&&bvl==1)?0.8f:0.2f;
    float w2=(v4==bv4&&bvl==2)?0.8f:0.2f, w3=(v4==bv4&&bvl==3)?0.8f:0.2f;
    s += x.x*w0 + x.y*w1 + x.z*w2 + x.w*w3;
  }
  __shared__ float sr[256];
  sr[t]=s; __syncthreads();
  for (int w=128;w>0;w>>=1){ if(t<w) sr[t]+=sr[t+w]; __syncthreads(); }
  float nm = mask[row] ? sr[0] : 1e-10f;
  float inv = 1.0f/nm;
#pragma unroll 4
  for (int i=0;i<16;i++){
    int v4=i*256+t;
    float4 x = __ldg(&p4[v4]);
    float w0=(v4==bv4&&bvl==0)?0.8f:0.2f, w1=(v4==bv4&&bvl==1)?0.8f:0.2f;
    float w2=(v4==bv4&&bvl==2)?0.8f:0.2f, w3=(v4==bv4&&bvl==3)?0.8f:0.2f;
    float4 y; y.x=x.x*w0*inv; y.y=x.y*w1*inv; y.z=x.z*w2*inv; y.w=x.w*w3*inv;
    o4[v4]=y;
  }
}

// ---------------- launch ----------------
extern "C" void kernel_launch(void* const* d_in, const int* in_sizes, int n_in,
                              void* d_out, int out_size){
  const float* probas = (const float*)d_in[0];
  const float* h_d    = (const float*)d_in[1];
  const int*   mask   = (const int*)d_in[2];
  const int*   bvocab = (const int*)d_in[3];
  const float* emb    = (const float*)d_in[4];
  const float* W1     = (const float*)d_in[5];
  const float* b1     = (const float*)d_in[6];
  float* out = (float*)d_out;
  (void)in_sizes; (void)n_in;

  // jax.random.split(jax.random.key(42), 8), partitionable/foldlike:
  // key_k = threefry2x32((0,42), (0,k)) -> (x0, x1)
  Keys keys;
  for (int k=0;k<NIT;k++){
    unsigned x0=0u, x1=(unsigned)k;
    tf2x32(0u,42u,x0,x1);
    keys.a[2*k]=x0; keys.a[2*k+1]=x1;
  }

  k_topk  <<<NROWS,256>>>(probas, mask);
  k_sample<<<512,  256>>>(mask, bvocab, keys);
  k_hw    <<<64,   256>>>(h_d, mask, W1);
  k_ne    <<<256,  256>>>(emb, mask, W1, b1);
  k_det   <<<128,  256>>>(mask);
  k_carry <<<1,   1024>>>(out + (size_t)out_size - NBv);
  k_out   <<<NROWS,256>>>(probas, mask, out);
}

// round 7
// speedup vs baseline: 3.1916x; 1.8434x over previous
#include <cuda_runtime.h>
#include <math.h>

#define NBv 16
#define NLv 64
#define Vv  16384
#define Dv  256
#define TK  16
#define NIT 8
#define NROWS (NBv*NLv)   // 1024

// ---------------- scratch (static device memory; no allocs) ----------------
__device__ float  g_logits[NROWS][TK];
__device__ int    g_topidx[NROWS][TK];
__device__ int    g_map[NROWS];
__device__ float  g_rowsum[NROWS];
__device__ int    g_samples[NIT][NROWS];
__device__ int    g_gidx[NIT][NROWS];
__device__ float  g_HW[NBv][NLv*Dv];
__device__ float  g_NE[NIT*NBv][NLv*Dv];   // 8 MB
__device__ float  g_scores[NIT][NBv];
__device__ int    g_best[NROWS];

// ---------------- threefry2x32 (JAX 20-round), host+device ----------------
__host__ __device__ inline void tf2x32(unsigned k0, unsigned k1, unsigned& x0, unsigned& x1){
  unsigned ks2 = k0 ^ k1 ^ 0x1BD11BDAu;
#define ROTL32(x,d) (((x)<<(d))|((x)>>(32-(d))))
#define TFRND(r) { x0 += x1; x1 = ROTL32(x1,(r)); x1 ^= x0; }
  x0 += k0; x1 += k1;
  TFRND(13) TFRND(15) TFRND(26) TFRND(6)
  x0 += k1; x1 += ks2 + 1u;
  TFRND(17) TFRND(29) TFRND(16) TFRND(24)
  x0 += ks2; x1 += k0 + 2u;
  TFRND(13) TFRND(15) TFRND(26) TFRND(6)
  x0 += k0; x1 += k1 + 3u;
  TFRND(17) TFRND(29) TFRND(16) TFRND(24)
  x0 += k1; x1 += ks2 + 4u;
  TFRND(13) TFRND(15) TFRND(26) TFRND(6)
  x0 += ks2; x1 += k0 + 5u;
#undef TFRND
#undef ROTL32
}

struct Keys { unsigned a[2*NIT]; };

// ---------------- f32x2 helpers ----------------
__device__ __forceinline__ unsigned long long pk2(float x, float y){
  unsigned long long r; asm("mov.b64 %0, {%1, %2};" : "=l"(r) : "f"(x), "f"(y)); return r;
}
__device__ __forceinline__ unsigned long long fma2(unsigned long long a, unsigned long long b, unsigned long long c){
  unsigned long long d; asm("fma.rn.f32x2 %0, %1, %2, %3;" : "=l"(d) : "l"(a), "l"(b), "l"(c)); return d;
}
__device__ __forceinline__ float2 upk(unsigned long long v){
  float2 f; asm("mov.b64 {%0, %1}, %2;" : "=f"(f.x), "=f"(f.y) : "l"(v)); return f;
}

// ---------------- kernel 1: per-row top-16 + argmax + logits + rowsum --------
// Fast path: threshold filter (>0.997) into smem candidate buffer, exact
// 16-round warp tournament over candidates. Exact slow fallback otherwise.
__global__ __launch_bounds__(256) void k_topk(const float* __restrict__ probas,
                                              const int* __restrict__ mask){
  int row = blockIdx.x;
  const float4* p4 = (const float4*)(probas + (size_t)row * Vv);
  int t = threadIdx.x;
  int lane = t & 31, warp = t >> 5;

  __shared__ unsigned long long cand[512];
  __shared__ int scnt;
  __shared__ float ssum[8];
  __shared__ unsigned long long sw8[8][TK];
  if (t==0) scnt=0;
  __syncthreads();

  const unsigned TH = __float_as_uint(0.997f);
  float sum = 0.f;
#pragma unroll 4
  for (int i=0;i<16;i++){
    int v4 = i*256 + t;
    float4 x = __ldg(&p4[v4]);
    sum += (x.x + x.y) + (x.z + x.w);
    float xs[4] = {x.x, x.y, x.z, x.w};
#pragma unroll
    for (int q=0;q<4;q++){
      unsigned fb = __float_as_uint(xs[q]);
      if (fb > TH){
        int pos = atomicAdd(&scnt, 1);
        if (pos < 512)
          cand[pos] = ((unsigned long long)fb<<32) | (unsigned)(~(v4*4+q));
      }
    }
  }
#pragma unroll
  for (int d=16; d>0; d>>=1) sum += __shfl_xor_sync(0xffffffffu, sum, d);
  if (lane==0) ssum[warp]=sum;
  __syncthreads();
  if (t==0){
    float s2=0.f;
#pragma unroll
    for (int i=0;i<8;i++) s2+=ssum[i];
    g_rowsum[row]=s2;
  }
  int cnt = scnt;

  if (cnt>=16 && cnt<=512){
    // exact top-16 of candidates by one warp
    if (warp==0){
      int jn = (cnt+31)>>5;
      unsigned long long lm=0ull;
      for (int j=0;j<jn;j++){
        int s=lane+32*j;
        unsigned long long k2 = (s<cnt)? cand[s] : 0ull;
        if (k2>lm) lm=k2;
      }
      unsigned long long mine=0ull;
      for (int r=0;r<TK;r++){
        unsigned long long bk=lm;
#pragma unroll
        for (int d=16;d>0;d>>=1){
          unsigned long long o=__shfl_xor_sync(0xffffffffu,bk,d);
          if (o>bk) bk=o;
        }
        if (lm==bk){       // unique winner (keys distinct)
          lm=0ull;
          for (int j=0;j<jn;j++){
            int s=lane+32*j;
            unsigned long long k2=(s<cnt)? cand[s] : 0ull;
            if (k2==bk) cand[s]=0ull;
            else if (k2>lm) lm=k2;
          }
        }
        if (lane==r) mine=bk;
      }
      if (lane<TK){
        int idx = (int)(~(unsigned)mine);
        float val = __uint_as_float((unsigned)(mine>>32));
        g_topidx[row][lane]=idx;
        g_logits[row][lane] = mask[row] ? logf(val) : 0.0f;
        if (lane==0) g_map[row]=idx;
      }
    }
    return;
  }

  // -------- exact slow fallback (never taken on expected data) --------
  unsigned long long v[TK];     // descending, v[0]=max
#pragma unroll
  for (int i=0;i<TK;i++) v[i]=0ull;
#pragma unroll 2
  for (int i=0;i<16;i++){
    int v4 = i*256 + t;
    float4 x = __ldg(&p4[v4]);
    float xs[4] = {x.x, x.y, x.z, x.w};
#pragma unroll
    for (int q=0;q<4;q++){
      unsigned fb = __float_as_uint(xs[q]);
      unsigned long long carry = ((unsigned long long)fb<<32) | (unsigned)(~(v4*4+q));
#pragma unroll
      for (int u=0;u<TK;u++){
        unsigned long long hi = (v[u]>carry)? v[u]:carry;
        unsigned long long lo = (v[u]>carry)? carry:v[u];
        v[u]=hi; carry=lo;
      }
    }
  }
  unsigned long long mine = 0ull;
  for (int r=0;r<TK;r++){
    unsigned long long bh = v[0]; int bl = lane;
#pragma unroll
    for (int d=16; d>0; d>>=1){
      unsigned long long oh = __shfl_xor_sync(0xffffffffu, bh, d);
      int ol = __shfl_xor_sync(0xffffffffu, bl, d);
      if (oh > bh){ bh=oh; bl=ol; }
    }
    if (lane==bl){
#pragma unroll
      for (int u=0;u<TK-1;u++) v[u]=v[u+1];
      v[TK-1]=0ull;
    }
    if (lane==r) mine = bh;
  }
  if (lane<TK) sw8[warp][lane] = mine;
  __syncthreads();
  if (warp==0){
    unsigned long long c[4];
    int wsrc = lane>>2, base=(lane&3)*4;
#pragma unroll
    for (int j=0;j<4;j++) c[j]=sw8[wsrc][base+j];
    unsigned long long res = 0ull;
    for (int r=0;r<TK;r++){
      unsigned long long bh=c[0]; int bl=lane;
#pragma unroll
      for (int d=16; d>0; d>>=1){
        unsigned long long oh = __shfl_xor_sync(0xffffffffu, bh, d);
        int ol = __shfl_xor_sync(0xffffffffu, bl, d);
        if (oh > bh){ bh=oh; bl=ol; }
      }
      if (lane==bl){ c[0]=c[1]; c[1]=c[2]; c[2]=c[3]; c[3]=0ull; }
      if (lane==r) res = bh;
    }
    if (lane<TK){
      int idx = (int)(~(unsigned)res);
      float val = __uint_as_float((unsigned)(res>>32));
      g_topidx[row][lane]=idx;
      g_logits[row][lane] = mask[row] ? logf(val) : 0.0f;
      if (lane==0) g_map[row]=idx;
    }
  }
}

// ---------------- kernel 2: gumbel-categorical sampling ----------------
__global__ __launch_bounds__(256) void k_sample(const int* __restrict__ mask,
                                                 const int* __restrict__ bvocab, Keys keys){
  int flat = blockIdx.x*256 + threadIdx.x;   // 0..131071
  int j   = flat & 15;
  int row = (flat>>4) & (NROWS-1);
  int k   = flat >> 14;
  unsigned k0=keys.a[2*k], k1=keys.a[2*k+1];
  unsigned x0=0u, x1=(unsigned)(row*TK + j);
  tf2x32(k0,k1,x0,x1);
  unsigned bits = x0 ^ x1;
  unsigned ub = (bits>>9) | 0x3f800000u;
  float f = __uint_as_float(ub) - 1.0f;
  float u = (f>0.f)? f : 1.17549435e-38f;     // uniform(minval=tiny,maxval=1)
  float s = -logf(-logf(u)) + g_logits[row][j];
  int arg = j;
#pragma unroll
  for (int w=1; w<16; w<<=1){
    float os = __shfl_xor_sync(0xffffffffu, s, w);
    int   oa = __shfl_xor_sync(0xffffffffu, arg, w);
    if (os>s || (os==s && oa<arg)){ s=os; arg=oa; }
  }
  if (j==0){
    int smp = g_topidx[row][arg];
    int ll = row&63;
    bool oh = mask[row] && (ll==63 || mask[row+1]==0);  // l == sLens-1 (prefix mask)
    if (oh) smp = g_map[row];
    g_samples[k][row]=smp;
    g_gidx[k][row]=bvocab[smp];
  }
}

// ---------------- kernel 3: HW[b] = (h_d*mask) @ W1[256:512] ----------------
__global__ __launch_bounds__(256) void k_hw(const float* __restrict__ h_d,
                                            const int* __restrict__ mask,
                                            const float* __restrict__ W1){
  int blk = blockIdx.x; int b = blk>>2; int cc = (blk&3)*64;
  int t = threadIdx.x; int ty=t>>4, tx=t&15;
  __shared__ float As[32][65];
  __shared__ float Bs[32][64];
  __shared__ float mf[64];
  if (t<64) mf[t] = (float)mask[b*64+t];
  __syncthreads();
  float acc[4][4];
#pragma unroll
  for (int i=0;i<4;i++)
#pragma unroll
    for (int j=0;j<4;j++) acc[i][j]=0.f;
  for (int k0=0;k0<Dv;k0+=32){
#pragma unroll
    for (int i=0;i<8;i++){
      int e=t+i*256; int r=e>>5, kk=e&31;
      As[kk][r] = h_d[((size_t)b*64+r)*Dv + k0+kk] * mf[r];
    }
#pragma unroll
    for (int i=0;i<8;i++){
      int e=t+i*256; int kk=e>>6, c=e&63;
      Bs[kk][c] = W1[(size_t)(Dv + k0+kk)*Dv + cc + c];
    }
    __syncthreads();
#pragma unroll
    for (int kk=0;kk<32;kk++){
      float a0=As[kk][ty],a1=As[kk][ty+16],a2=As[kk][ty+32],a3=As[kk][ty+48];
      float w0=Bs[kk][tx],w1=Bs[kk][tx+16],w2=Bs[kk][tx+32],w3=Bs[kk][tx+48];
      acc[0][0]+=a0*w0; acc[0][1]+=a0*w1; acc[0][2]+=a0*w2; acc[0][3]+=a0*w3;
      acc[1][0]+=a1*w0; acc[1][1]+=a1*w1; acc[1][2]+=a1*w2; acc[1][3]+=a1*w3;
      acc[2][0]+=a2*w0; acc[2][1]+=a2*w1; acc[2][2]+=a2*w2; acc[2][3]+=a2*w3;
      acc[3][0]+=a3*w0; acc[3][1]+=a3*w1; acc[3][2]+=a3*w2; acc[3][3]+=a3*w3;
    }
    __syncthreads();
  }
#pragma unroll
  for (int ri=0;ri<4;ri++)
#pragma unroll
    for (int ci=0;ci<4;ci++)
      g_HW[b][(ty+16*ri)*Dv + cc + tx+16*ci] = acc[ri][ci];
}

// ---------------- kernel 4: NE = relu(E@W1[0:256] + HW + b1) ----------------
// 64x128 tile, f32x2 packed FMA (16 fma2/kk), register double-buffered tiles.
// Thread (ty,tx) owns rows ty+16*ri, col pairs cc+32*p+2*tx+{0,1}.
__global__ __launch_bounds__(256) void k_ne(const float* __restrict__ emb,
                                            const int* __restrict__ mask,
                                            const float* __restrict__ W1,
                                            const float* __restrict__ b1){
  int blk=blockIdx.x;
  int task=blk>>1; int cc=(blk&1)*128;
  int k=task>>4, b=task&15;
  int t=threadIdx.x; int ty=t>>4, tx=t&15;
  __shared__ float As[32][65];
  __shared__ __align__(16) float Bs[32][132];
  __shared__ int gid[64]; __shared__ float mf[64];
  if (t<64){ gid[t]=g_gidx[k][b*64+t]; mf[t]=(float)mask[b*64+t]; }
  __syncthreads();
  unsigned long long acc[4][4];
#pragma unroll
  for (int i=0;i<4;i++)
#pragma unroll
    for (int j=0;j<4;j++) acc[i][j]=0ull;

  float pa[8]; float4 pb[4];
#pragma unroll
  for (int i=0;i<8;i++){ int e=t+i*256; int r=e>>5, kk=e&31;
    pa[i]=emb[(size_t)gid[r]*Dv + kk]*mf[r]; }
#pragma unroll
  for (int i=0;i<4;i++){ int e=t+i*256; int kk=e>>5, c4=e&31;
    pb[i]=*(const float4*)&W1[(size_t)kk*Dv + cc + c4*4]; }

  for (int k0=0;k0<Dv;k0+=32){
#pragma unroll
    for (int i=0;i<8;i++){ int e=t+i*256; int r=e>>5, kk=e&31; As[kk][r]=pa[i]; }
#pragma unroll
    for (int i=0;i<4;i++){ int e=t+i*256; int kk=e>>5, c4=e&31; *(float4*)&Bs[kk][c4*4]=pb[i]; }
    __syncthreads();
    if (k0+32<Dv){
      int kn=k0+32;
#pragma unroll
      for (int i=0;i<8;i++){ int e=t+i*256; int r=e>>5, kk=e&31;
        pa[i]=emb[(size_t)gid[r]*Dv + kn+kk]*mf[r]; }
#pragma unroll
      for (int i=0;i<4;i++){ int e=t+i*256; int kk=e>>5, c4=e&31;
        pb[i]=*(const float4*)&W1[(size_t)(kn+kk)*Dv + cc + c4*4]; }
    }
#pragma unroll
    for (int kk=0;kk<32;kk++){
      unsigned long long ap[4], wq[4];
#pragma unroll
      for (int ri=0;ri<4;ri++){ float a=As[kk][ty+16*ri]; ap[ri]=pk2(a,a); }
#pragma unroll
      for (int p=0;p<4;p++) wq[p]=*(const unsigned long long*)&Bs[kk][32*p+2*tx];
#pragma unroll
      for (int ri=0;ri<4;ri++)
#pragma unroll
        for (int p=0;p<4;p++) acc[ri][p]=fma2(ap[ri],wq[p],acc[ri][p]);
    }
    __syncthreads();
  }
#pragma unroll
  for (int ri=0;ri<4;ri++)
#pragma unroll
    for (int p=0;p<4;p++){
      int r=ty+16*ri, c=cc+32*p+2*tx;
      float2 av = upk(acc[ri][p]);
      float2 hw = *(const float2*)&g_HW[b][r*Dv+c];
      float2 bb = *(const float2*)&b1[c];
      float2 o;
      o.x = fmaxf(av.x+hw.x+bb.x, 0.f);
      o.y = fmaxf(av.y+hw.y+bb.y, 0.f);
      *(float2*)&g_NE[task][(size_t)r*Dv+c] = o;
    }
}

// ---------------- kernel 5: Gram + masked-identity + no-pivot LU det --------
// K+masked-eye is PSD -> LU without pivoting is stable; run to sLen only.
__global__ __launch_bounds__(256) void k_det(const int* __restrict__ mask){
  int task = blockIdx.x;          // k*16+b
  int b = task & 15;
  int t = threadIdx.x;
  int ti = t>>4, tj = t&15;
  __shared__ float As[64][33];
  __shared__ float M[64][65];
  __shared__ int vld[64];
  if (t<64) vld[t]=mask[b*64+t];
  float acc[4][4];
#pragma unroll
  for (int i=0;i<4;i++)
#pragma unroll
    for (int j=0;j<4;j++) acc[i][j]=0.f;
  const float* NE = g_NE[task];
  for (int k0=0;k0<Dv;k0+=32){
#pragma unroll
    for (int i=0;i<8;i++){
      int e=t+i*256; int r=e>>5, kk=e&31;
      As[r][kk] = NE[(size_t)r*Dv + k0+kk];
    }
    __syncthreads();
#pragma unroll
    for (int kk=0;kk<32;kk++){
      float a0=As[ti][kk],a1=As[ti+16][kk],a2=As[ti+32][kk],a3=As[ti+48][kk];
      float c0=As[tj][kk],c1=As[tj+16][kk],c2=As[tj+32][kk],c3=As[tj+48][kk];
      acc[0][0]+=a0*c0; acc[0][1]+=a0*c1; acc[0][2]+=a0*c2; acc[0][3]+=a0*c3;
      acc[1][0]+=a1*c0; acc[1][1]+=a1*c1; acc[1][2]+=a1*c2; acc[1][3]+=a1*c3;
      acc[2][0]+=a2*c0; acc[2][1]+=a2*c1; acc[2][2]+=a2*c2; acc[2][3]+=a2*c3;
      acc[3][0]+=a3*c0; acc[3][1]+=a3*c1; acc[3][2]+=a3*c2; acc[3][3]+=a3*c3;
    }
    __syncthreads();
  }
#pragma unroll
  for (int ri=0;ri<4;ri++)
#pragma unroll
    for (int ci=0;ci<4;ci++){
      int r=ti+16*ri, c=tj+16*ci;
      float v = acc[ri][ci];
      if (!(vld[r] && vld[c])) v = (r==c)?1.f:0.f;   // where(m2d,K,eye)
      M[r][c]=v;
    }

  __shared__ float fct[64];
  __shared__ int sn;
  __shared__ double sdet;
  if (t==0){ sdet=1.0; sn=0; }
  __syncthreads();
  if (t<64 && vld[t] && (t==63 || !vld[t+1])) sn=t+1;   // sLen (prefix mask)
  __syncthreads();
  int sl = sn;
  for (int i=0;i<sl;i++){
    float piv = M[i][i];
    if (t<64 && t>i) fct[t]=M[t][i]/piv;
    if (t==0) sdet *= (double)piv;
    __syncthreads();
    int tr=t>>6, tc=t&63;
    if (tc>i){
      float mi=M[i][tc];
      for (int r=i+1+tr; r<sl; r+=4)
        M[r][tc] -= fct[r]*mi;
    }
    __syncthreads();
  }
  if (t==0) g_scores[task>>4][b] = (float)sdet;
}

// ---------------- kernel 6: scan-carry (improved/count/stopped) ----------------
__global__ __launch_bounds__(1024) void k_carry(float* __restrict__ out_scores){
  int t=threadIdx.x;
  __shared__ float ms[NBv];
  __shared__ int sbest[NROWS];
  __shared__ int imp[NBv];
  __shared__ int s_ost, s_count, s_stop;
  if (t<NBv) ms[t]=-INFINITY;
  sbest[t]=g_map[t];
  if (t==0){s_count=0;s_stop=0;s_ost=0;}
  __syncthreads();
  for (int k=0;k<NIT;k++){
    if (t<NBv) imp[t] = (g_scores[k][t] > ms[t])?1:0;
    __syncthreads();
    if (t==0){
      int a=0; for (int bb=0;bb<NBv;bb++) a|=imp[bb];
      s_ost = s_stop;                               // upd uses OLD stopped
      s_count = a?0:(s_count+1);
      if ((!a) && s_count>=2) s_stop=1;
    }
    __syncthreads();
    if (t<NBv && imp[t] && !s_ost) ms[t]=g_scores[k][t];
    if (imp[t>>6] && !s_ost) sbest[t]=g_samples[k][t];
    __syncthreads();
  }
  g_best[t]=sbest[t];
  if (t<NBv) out_scores[t]=ms[t];
}

// ---------------- kernel 7: diverse_proba scatter-renormalize (1 pass) ------
__global__ __launch_bounds__(256) void k_out(const float* __restrict__ probas,
                                             const int* __restrict__ mask,
                                             float* __restrict__ out){
  int row=blockIdx.x;
  const float4* p4 = (const float4*)(probas + (size_t)row*Vv);
  float4* o4 = (float4*)(out + (size_t)row*Vv);
  int t=threadIdx.x;
  int bv = g_best[row];
  int bv4 = bv>>2, bvl = bv&3;
  float nm;
  if (mask[row]){
    float pbst = __ldg(&probas[(size_t)row*Vv + bv]);
    nm = 0.2f*g_rowsum[row] + 0.6f*pbst;
  } else nm = 1e-10f;
  float inv = 1.0f/nm;
#pragma unroll 4
  for (int i=0;i<16;i++){
    int v4=i*256+t;
    float4 x = __ldg(&p4[v4]);
    float w0=(v4==bv4&&bvl==0)?0.8f:0.2f, w1=(v4==bv4&&bvl==1)?0.8f:0.2f;
    float w2=(v4==bv4&&bvl==2)?0.8f:0.2f, w3=(v4==bv4&&bvl==3)?0.8f:0.2f;
    float4 y; y.x=x.x*w0*inv; y.y=x.y*w1*inv; y.z=x.z*w2*inv; y.w=x.w*w3*inv;
    o4[v4]=y;
  }
}

// ---------------- launch ----------------
extern "C" void kernel_launch(void* const* d_in, const int* in_sizes, int n_in,
                              void* d_out, int out_size){
  const float* probas = (const float*)d_in[0];
  const float* h_d    = (const float*)d_in[1];
  const int*   mask   = (const int*)d_in[2];
  const int*   bvocab = (const int*)d_in[3];
  const float* emb    = (const float*)d_in[4];
  const float* W1     = (const float*)d_in[5];
  const float* b1     = (const float*)d_in[6];
  float* out = (float*)d_out;
  (void)in_sizes; (void)n_in;

  // jax.random.split(jax.random.key(42), 8), partitionable/foldlike:
  // key_k = threefry2x32((0,42), (0,k)) -> (x0, x1)
  Keys keys;
  for (int k=0;k<NIT;k++){
    unsigned x0=0u, x1=(unsigned)k;
    tf2x32(0u,42u,x0,x1);
    keys.a[2*k]=x0; keys.a[2*k+1]=x1;
  }

  k_topk  <<<NROWS,256>>>(probas, mask);
  k_sample<<<512,  256>>>(mask, bvocab, keys);
  k_hw    <<<64,   256>>>(h_d, mask, W1);
  k_ne    <<<256,  256>>>(emb, mask, W1, b1);
  k_det   <<<128,  256>>>(mask);
  k_carry <<<1,   1024>>>(out + (size_t)out_size - NBv);
  k_out   <<<NROWS,256>>>(probas, mask, out);
}

// round 8
// speedup vs baseline: 3.7304x; 1.1688x over previous
#include <cuda_runtime.h>
#include <math.h>

#define NBv 16
#define NLv 64
#define Vv  16384
#define Dv  256
#define TK  16
#define NIT 8
#define NROWS (NBv*NLv)   // 1024

// ---------------- scratch (static device memory; no allocs) ----------------
__device__ float  g_logits[NROWS][TK];
__device__ int    g_topidx[NROWS][TK];
__device__ int    g_map[NROWS];
__device__ float  g_rowsum[NROWS];
__device__ int    g_samples[NIT][NROWS];
__device__ int    g_gidx[NIT][NROWS];
__device__ float  g_HW[NBv][NLv*Dv];
__device__ float  g_scores[NIT][NBv];
__device__ int    g_best[NROWS];

// ---------------- threefry2x32 (JAX 20-round), host+device ----------------
__host__ __device__ inline void tf2x32(unsigned k0, unsigned k1, unsigned& x0, unsigned& x1){
  unsigned ks2 = k0 ^ k1 ^ 0x1BD11BDAu;
#define ROTL32(x,d) (((x)<<(d))|((x)>>(32-(d))))
#define TFRND(r) { x0 += x1; x1 = ROTL32(x1,(r)); x1 ^= x0; }
  x0 += k0; x1 += k1;
  TFRND(13) TFRND(15) TFRND(26) TFRND(6)
  x0 += k1; x1 += ks2 + 1u;
  TFRND(17) TFRND(29) TFRND(16) TFRND(24)
  x0 += ks2; x1 += k0 + 2u;
  TFRND(13) TFRND(15) TFRND(26) TFRND(6)
  x0 += k0; x1 += k1 + 3u;
  TFRND(17) TFRND(29) TFRND(16) TFRND(24)
  x0 += k1; x1 += ks2 + 4u;
  TFRND(13) TFRND(15) TFRND(26) TFRND(6)
  x0 += ks2; x1 += k0 + 5u;
#undef TFRND
#undef ROTL32
}

struct Keys { unsigned a[2*NIT]; };

// ---------------- f32x2 helpers ----------------
__device__ __forceinline__ unsigned long long pk2(float x, float y){
  unsigned long long r; asm("mov.b64 %0, {%1, %2};" : "=l"(r) : "f"(x), "f"(y)); return r;
}
__device__ __forceinline__ unsigned long long fma2(unsigned long long a, unsigned long long b, unsigned long long c){
  unsigned long long d; asm("fma.rn.f32x2 %0, %1, %2, %3;" : "=l"(d) : "l"(a), "l"(b), "l"(c)); return d;
}
__device__ __forceinline__ float2 upk(unsigned long long v){
  float2 f; asm("mov.b64 {%0, %1}, %2;" : "=f"(f.x), "=f"(f.y) : "l"(v)); return f;
}

// ---------------- kernel 1: per-row top-16 + argmax + logits + rowsum --------
__global__ __launch_bounds__(256) void k_topk(const float* __restrict__ probas,
                                              const int* __restrict__ mask){
  int row = blockIdx.x;
  const float4* p4 = (const float4*)(probas + (size_t)row * Vv);
  int t = threadIdx.x;
  int lane = t & 31, warp = t >> 5;

  __shared__ unsigned long long cand[512];
  __shared__ int scnt;
  __shared__ float ssum[8];
  __shared__ unsigned long long sw8[8][TK];
  if (t==0) scnt=0;
  __syncthreads();

  const unsigned TH = __float_as_uint(0.997f);
  float sum = 0.f;
#pragma unroll 4
  for (int i=0;i<16;i++){
    int v4 = i*256 + t;
    float4 x = __ldg(&p4[v4]);
    sum += (x.x + x.y) + (x.z + x.w);
    float xs[4] = {x.x, x.y, x.z, x.w};
#pragma unroll
    for (int q=0;q<4;q++){
      unsigned fb = __float_as_uint(xs[q]);
      if (fb > TH){
        int pos = atomicAdd(&scnt, 1);
        if (pos < 512)
          cand[pos] = ((unsigned long long)fb<<32) | (unsigned)(~(v4*4+q));
      }
    }
  }
#pragma unroll
  for (int d=16; d>0; d>>=1) sum += __shfl_xor_sync(0xffffffffu, sum, d);
  if (lane==0) ssum[warp]=sum;
  __syncthreads();
  if (t==0){
    float s2=0.f;
#pragma unroll
    for (int i=0;i<8;i++) s2+=ssum[i];
    g_rowsum[row]=s2;
  }
  int cnt = scnt;

  if (cnt>=16 && cnt<=512){
    if (warp==0){
      int jn = (cnt+31)>>5;
      unsigned long long lm=0ull;
      for (int j=0;j<jn;j++){
        int s=lane+32*j;
        unsigned long long k2 = (s<cnt)? cand[s] : 0ull;
        if (k2>lm) lm=k2;
      }
      unsigned long long mine=0ull;
      for (int r=0;r<TK;r++){
        unsigned long long bk=lm;
#pragma unroll
        for (int d=16;d>0;d>>=1){
          unsigned long long o=__shfl_xor_sync(0xffffffffu,bk,d);
          if (o>bk) bk=o;
        }
        if (lm==bk){
          lm=0ull;
          for (int j=0;j<jn;j++){
            int s=lane+32*j;
            unsigned long long k2=(s<cnt)? cand[s] : 0ull;
            if (k2==bk) cand[s]=0ull;
            else if (k2>lm) lm=k2;
          }
        }
        if (lane==r) mine=bk;
      }
      if (lane<TK){
        int idx = (int)(~(unsigned)mine);
        float val = __uint_as_float((unsigned)(mine>>32));
        g_topidx[row][lane]=idx;
        g_logits[row][lane] = mask[row] ? logf(val) : 0.0f;
        if (lane==0) g_map[row]=idx;
      }
    }
    return;
  }

  // -------- exact slow fallback (never taken on expected data) --------
  unsigned long long v[TK];
#pragma unroll
  for (int i=0;i<TK;i++) v[i]=0ull;
#pragma unroll 2
  for (int i=0;i<16;i++){
    int v4 = i*256 + t;
    float4 x = __ldg(&p4[v4]);
    float xs[4] = {x.x, x.y, x.z, x.w};
#pragma unroll
    for (int q=0;q<4;q++){
      unsigned fb = __float_as_uint(xs[q]);
      unsigned long long carry = ((unsigned long long)fb<<32) | (unsigned)(~(v4*4+q));
#pragma unroll
      for (int u=0;u<TK;u++){
        unsigned long long hi = (v[u]>carry)? v[u]:carry;
        unsigned long long lo = (v[u]>carry)? carry:v[u];
        v[u]=hi; carry=lo;
      }
    }
  }
  unsigned long long mine = 0ull;
  for (int r=0;r<TK;r++){
    unsigned long long bh = v[0]; int bl = lane;
#pragma unroll
    for (int d=16; d>0; d>>=1){
      unsigned long long oh = __shfl_xor_sync(0xffffffffu, bh, d);
      int ol = __shfl_xor_sync(0xffffffffu, bl, d);
      if (oh > bh){ bh=oh; bl=ol; }
    }
    if (lane==bl){
#pragma unroll
      for (int u=0;u<TK-1;u++) v[u]=v[u+1];
      v[TK-1]=0ull;
    }
    if (lane==r) mine = bh;
  }
  if (lane<TK) sw8[warp][lane] = mine;
  __syncthreads();
  if (warp==0){
    unsigned long long c[4];
    int wsrc = lane>>2, base=(lane&3)*4;
#pragma unroll
    for (int j=0;j<4;j++) c[j]=sw8[wsrc][base+j];
    unsigned long long res = 0ull;
    for (int r=0;r<TK;r++){
      unsigned long long bh=c[0]; int bl=lane;
#pragma unroll
      for (int d=16; d>0; d>>=1){
        unsigned long long oh = __shfl_xor_sync(0xffffffffu, bh, d);
        int ol = __shfl_xor_sync(0xffffffffu, bl, d);
        if (oh > bh){ bh=oh; bl=ol; }
      }
      if (lane==bl){ c[0]=c[1]; c[1]=c[2]; c[2]=c[3]; c[3]=0ull; }
      if (lane==r) res = bh;
    }
    if (lane<TK){
      int idx = (int)(~(unsigned)res);
      float val = __uint_as_float((unsigned)(res>>32));
      g_topidx[row][lane]=idx;
      g_logits[row][lane] = mask[row] ? logf(val) : 0.0f;
      if (lane==0) g_map[row]=idx;
    }
  }
}

// ---------------- kernel 2: gumbel-categorical sampling ----------------
__global__ __launch_bounds__(256) void k_sample(const int* __restrict__ mask,
                                                 const int* __restrict__ bvocab, Keys keys){
  int flat = blockIdx.x*256 + threadIdx.x;   // 0..131071
  int j   = flat & 15;
  int row = (flat>>4) & (NROWS-1);
  int k   = flat >> 14;
  unsigned k0=keys.a[2*k], k1=keys.a[2*k+1];
  unsigned x0=0u, x1=(unsigned)(row*TK + j);
  tf2x32(k0,k1,x0,x1);
  unsigned bits = x0 ^ x1;
  unsigned ub = (bits>>9) | 0x3f800000u;
  float f = __uint_as_float(ub) - 1.0f;
  float u = (f>0.f)? f : 1.17549435e-38f;
  float s = -logf(-logf(u)) + g_logits[row][j];
  int arg = j;
#pragma unroll
  for (int w=1; w<16; w<<=1){
    float os = __shfl_xor_sync(0xffffffffu, s, w);
    int   oa = __shfl_xor_sync(0xffffffffu, arg, w);
    if (os>s || (os==s && oa<arg)){ s=os; arg=oa; }
  }
  if (j==0){
    int smp = g_topidx[row][arg];
    int ll = row&63;
    bool oh = mask[row] && (ll==63 || mask[row+1]==0);
    if (oh) smp = g_map[row];
    g_samples[k][row]=smp;
    g_gidx[k][row]=bvocab[smp];
  }
}

// ---------------- kernel 3: HW[b] = (h_d*mask) @ W1[256:512] ----------------
__global__ __launch_bounds__(256) void k_hw(const float* __restrict__ h_d,
                                            const int* __restrict__ mask,
                                            const float* __restrict__ W1){
  int blk = blockIdx.x; int b = blk>>2; int cc = (blk&3)*64;
  int t = threadIdx.x; int ty=t>>4, tx=t&15;
  __shared__ float As[32][65];
  __shared__ float Bs[32][64];
  __shared__ float mf[64];
  if (t<64) mf[t] = (float)mask[b*64+t];
  __syncthreads();
  float acc[4][4];
#pragma unroll
  for (int i=0;i<4;i++)
#pragma unroll
    for (int j=0;j<4;j++) acc[i][j]=0.f;
  for (int k0=0;k0<Dv;k0+=32){
#pragma unroll
    for (int i=0;i<8;i++){
      int e=t+i*256; int r=e>>5, kk=e&31;
      As[kk][r] = h_d[((size_t)b*64+r)*Dv + k0+kk] * mf[r];
    }
#pragma unroll
    for (int i=0;i<8;i++){
      int e=t+i*256; int kk=e>>6, c=e&63;
      Bs[kk][c] = W1[(size_t)(Dv + k0+kk)*Dv + cc + c];
    }
    __syncthreads();
#pragma unroll
    for (int kk=0;kk<32;kk++){
      float a0=As[kk][ty],a1=As[kk][ty+16],a2=As[kk][ty+32],a3=As[kk][ty+48];
      float w0=Bs[kk][tx],w1=Bs[kk][tx+16],w2=Bs[kk][tx+32],w3=Bs[kk][tx+48];
      acc[0][0]+=a0*w0; acc[0][1]+=a0*w1; acc[0][2]+=a0*w2; acc[0][3]+=a0*w3;
      acc[1][0]+=a1*w0; acc[1][1]+=a1*w1; acc[1][2]+=a1*w2; acc[1][3]+=a1*w3;
      acc[2][0]+=a2*w0; acc[2][1]+=a2*w1; acc[2][2]+=a2*w2; acc[2][3]+=a2*w3;
      acc[3][0]+=a3*w0; acc[3][1]+=a3*w1; acc[3][2]+=a3*w2; acc[3][3]+=a3*w3;
    }
    __syncthreads();
  }
#pragma unroll
  for (int ri=0;ri<4;ri++)
#pragma unroll
    for (int ci=0;ci<4;ci++)
      g_HW[b][(ty+16*ri)*Dv + cc + tx+16*ci] = acc[ri][ci];
}

// ---------------- kernel 4: FUSED  NE = relu(E@W1a + HW + b1) -> Gram -> det
// One block per task (grid=128, single wave). NE tile kept in dynamic smem.
// Layout (floats): NEs 64x258 | As 32x65 | Bs 32x260 | M 64x65
#define OFF_AS  16512
#define OFF_BS  (OFF_AS + 32*65)
#define OFF_M   (OFF_BS + 32*260)
#define SM_FLOATS (OFF_M + 64*65)
#define NE_S(r,c) sm[(r)*258+(c)]
#define AS_S(kk,r) sm[OFF_AS + (kk)*65 + (r)]
#define BS_S(kk,c) sm[OFF_BS + (kk)*260 + (c)]
#define M_S(r,c)  sm[OFF_M + (r)*65 + (c)]

__global__ __launch_bounds__(256) void k_fused(const float* __restrict__ emb,
                                               const int* __restrict__ mask,
                                               const float* __restrict__ W1,
                                               const float* __restrict__ b1){
  extern __shared__ float sm[];
  int task=blockIdx.x;                 // k*16+b
  int k=task>>4, b=task&15;
  int t=threadIdx.x; int ty=t>>4, tx=t&15;
  __shared__ int gid[64]; __shared__ float mf[64]; __shared__ int vld[64];
  __shared__ float fct[64];
  __shared__ int sn;
  __shared__ double sdet;
  if (t<64){ gid[t]=g_gidx[k][b*64+t]; int m=mask[b*64+t]; mf[t]=(float)m; vld[t]=m; }
  if (t==0){ sdet=1.0; sn=0; }
  __syncthreads();

  // ---- phase 1: NE = relu(E@W1[0:256] + HW + b1), 64x256 in smem ----
  unsigned long long acc[4][8];
#pragma unroll
  for (int i=0;i<4;i++)
#pragma unroll
    for (int j=0;j<8;j++) acc[i][j]=0ull;

  float pa[8]; float4 pb[8];
#pragma unroll
  for (int i=0;i<8;i++){ int e=t+i*256; int r=e>>5, kk=e&31;
    pa[i]=emb[(size_t)gid[r]*Dv + kk]*mf[r]; }
#pragma unroll
  for (int i=0;i<8;i++){ int e=t+i*256; int kk=e>>6, c4=e&63;
    pb[i]=*(const float4*)&W1[(size_t)kk*Dv + c4*4]; }

  for (int k0=0;k0<Dv;k0+=32){
#pragma unroll
    for (int i=0;i<8;i++){ int e=t+i*256; int r=e>>5, kk=e&31; AS_S(kk,r)=pa[i]; }
#pragma unroll
    for (int i=0;i<8;i++){ int e=t+i*256; int kk=e>>6, c4=e&63;
      *(float4*)&BS_S(kk,c4*4)=pb[i]; }
    __syncthreads();
    if (k0+32<Dv){
      int kn=k0+32;
#pragma unroll
      for (int i=0;i<8;i++){ int e=t+i*256; int r=e>>5, kk=e&31;
        pa[i]=emb[(size_t)gid[r]*Dv + kn+kk]*mf[r]; }
#pragma unroll
      for (int i=0;i<8;i++){ int e=t+i*256; int kk=e>>6, c4=e&63;
        pb[i]=*(const float4*)&W1[(size_t)(kn+kk)*Dv + c4*4]; }
    }
#pragma unroll
    for (int kk=0;kk<32;kk++){
      unsigned long long ap[4], wq[8];
#pragma unroll
      for (int ri=0;ri<4;ri++){ float a=AS_S(kk,ty+16*ri); ap[ri]=pk2(a,a); }
#pragma unroll
      for (int p=0;p<8;p++) wq[p]=*(const unsigned long long*)&BS_S(kk,32*p+2*tx);
#pragma unroll
      for (int ri=0;ri<4;ri++)
#pragma unroll
        for (int p=0;p<8;p++) acc[ri][p]=fma2(ap[ri],wq[p],acc[ri][p]);
    }
    __syncthreads();
  }
#pragma unroll
  for (int ri=0;ri<4;ri++)
#pragma unroll
    for (int p=0;p<8;p++){
      int r=ty+16*ri, c=32*p+2*tx;
      float2 av = upk(acc[ri][p]);
      float2 hw = *(const float2*)&g_HW[b][r*Dv+c];
      float2 bb = *(const float2*)&b1[c];
      float2 o;
      o.x = fmaxf(av.x+hw.x+bb.x, 0.f);
      o.y = fmaxf(av.y+hw.y+bb.y, 0.f);
      *(float2*)&NE_S(r,c) = o;
    }
  __syncthreads();

  // ---- phase 2: Gram (f32x2 over kk pairs) + masked identity ----
  int ti=ty, tj=tx;
  unsigned long long g2[4][4];
#pragma unroll
  for (int i=0;i<4;i++)
#pragma unroll
    for (int j=0;j<4;j++) g2[i][j]=0ull;
  for (int k2=0;k2<128;k2++){
    unsigned long long a0=*(const unsigned long long*)&NE_S(ti,    2*k2);
    unsigned long long a1=*(const unsigned long long*)&NE_S(ti+16, 2*k2);
    unsigned long long a2=*(const unsigned long long*)&NE_S(ti+32, 2*k2);
    unsigned long long a3=*(const unsigned long long*)&NE_S(ti+48, 2*k2);
    unsigned long long c0=*(const unsigned long long*)&NE_S(tj,    2*k2);
    unsigned long long c1=*(const unsigned long long*)&NE_S(tj+16, 2*k2);
    unsigned long long c2=*(const unsigned long long*)&NE_S(tj+32, 2*k2);
    unsigned long long c3=*(const unsigned long long*)&NE_S(tj+48, 2*k2);
    g2[0][0]=fma2(a0,c0,g2[0][0]); g2[0][1]=fma2(a0,c1,g2[0][1]);
    g2[0][2]=fma2(a0,c2,g2[0][2]); g2[0][3]=fma2(a0,c3,g2[0][3]);
    g2[1][0]=fma2(a1,c0,g2[1][0]); g2[1][1]=fma2(a1,c1,g2[1][1]);
    g2[1][2]=fma2(a1,c2,g2[1][2]); g2[1][3]=fma2(a1,c3,g2[1][3]);
    g2[2][0]=fma2(a2,c0,g2[2][0]); g2[2][1]=fma2(a2,c1,g2[2][1]);
    g2[2][2]=fma2(a2,c2,g2[2][2]); g2[2][3]=fma2(a2,c3,g2[2][3]);
    g2[3][0]=fma2(a3,c0,g2[3][0]); g2[3][1]=fma2(a3,c1,g2[3][1]);
    g2[3][2]=fma2(a3,c2,g2[3][2]); g2[3][3]=fma2(a3,c3,g2[3][3]);
  }
  __syncthreads();   // NE region free to alias? (M region is separate; just ordering)
#pragma unroll
  for (int ri=0;ri<4;ri++)
#pragma unroll
    for (int ci=0;ci<4;ci++){
      int r=ti+16*ri, c=tj+16*ci;
      float2 gv = upk(g2[ri][ci]);
      float v = gv.x + gv.y;
      if (!(vld[r] && vld[c])) v = (r==c)?1.f:0.f;
      M_S(r,c)=v;
    }
  __syncthreads();

  // ---- phase 3: no-pivot LU det over leading sLen block ----
  if (t<64 && vld[t] && (t==63 || !vld[t+1])) sn=t+1;
  __syncthreads();
  int sl = sn;
  for (int i=0;i<sl;i++){
    float piv = M_S(i,i);
    if (t<64 && t>i) fct[t]=M_S(t,i)/piv;
    if (t==0) sdet *= (double)piv;
    __syncthreads();
    int tr=t>>6, tc=t&63;
    if (tc>i){
      float mi=M_S(i,tc);
      for (int r=i+1+tr; r<sl; r+=4)
        M_S(r,tc) -= fct[r]*mi;
    }
    __syncthreads();
  }
  if (t==0) g_scores[k][b] = (float)sdet;
}

// ---------------- kernel 6: scan-carry (improved/count/stopped) ----------------
__global__ __launch_bounds__(1024) void k_carry(float* __restrict__ out_scores){
  int t=threadIdx.x;
  __shared__ float ms[NBv];
  __shared__ int sbest[NROWS];
  __shared__ int imp[NBv];
  __shared__ int s_ost, s_count, s_stop;
  if (t<NBv) ms[t]=-INFINITY;
  sbest[t]=g_map[t];
  if (t==0){s_count=0;s_stop=0;s_ost=0;}
  __syncthreads();
  for (int k=0;k<NIT;k++){
    if (t<NBv) imp[t] = (g_scores[k][t] > ms[t])?1:0;
    __syncthreads();
    if (t==0){
      int a=0; for (int bb=0;bb<NBv;bb++) a|=imp[bb];
      s_ost = s_stop;
      s_count = a?0:(s_count+1);
      if ((!a) && s_count>=2) s_stop=1;
    }
    __syncthreads();
    if (t<NBv && imp[t] && !s_ost) ms[t]=g_scores[k][t];
    if (imp[t>>6] && !s_ost) sbest[t]=g_samples[k][t];
    __syncthreads();
  }
  g_best[t]=sbest[t];
  if (t<NBv) out_scores[t]=ms[t];
}

// ---------------- kernel 7: diverse_proba scatter-renormalize (1 pass) ------
__global__ __launch_bounds__(256) void k_out(const float* __restrict__ probas,
                                             const int* __restrict__ mask,
                                             float* __restrict__ out){
  int row=blockIdx.x;
  const float4* p4 = (const float4*)(probas + (size_t)row*Vv);
  float4* o4 = (float4*)(out + (size_t)row*Vv);
  int t=threadIdx.x;
  int bv = g_best[row];
  int bv4 = bv>>2, bvl = bv&3;
  float nm;
  if (mask[row]){
    float pbst = __ldg(&probas[(size_t)row*Vv + bv]);
    nm = 0.2f*g_rowsum[row] + 0.6f*pbst;
  } else nm = 1e-10f;
  float inv = 1.0f/nm;
#pragma unroll 4
  for (int i=0;i<16;i++){
    int v4=i*256+t;
    float4 x = __ldg(&p4[v4]);
    float w0=(v4==bv4&&bvl==0)?0.8f:0.2f, w1=(v4==bv4&&bvl==1)?0.8f:0.2f;
    float w2=(v4==bv4&&bvl==2)?0.8f:0.2f, w3=(v4==bv4&&bvl==3)?0.8f:0.2f;
    float4 y; y.x=x.x*w0*inv; y.y=x.y*w1*inv; y.z=x.z*w2*inv; y.w=x.w*w3*inv;
    o4[v4]=y;
  }
}

// ---------------- launch ----------------
extern "C" void kernel_launch(void* const* d_in, const int* in_sizes, int n_in,
                              void* d_out, int out_size){
  const float* probas = (const float*)d_in[0];
  const float* h_d    = (const float*)d_in[1];
  const int*   mask   = (const int*)d_in[2];
  const int*   bvocab = (const int*)d_in[3];
  const float* emb    = (const float*)d_in[4];
  const float* W1     = (const float*)d_in[5];
  const float* b1     = (const float*)d_in[6];
  float* out = (float*)d_out;
  (void)in_sizes; (void)n_in;

  Keys keys;
  for (int k=0;k<NIT;k++){
    unsigned x0=0u, x1=(unsigned)k;
    tf2x32(0u,42u,x0,x1);
    keys.a[2*k]=x0; keys.a[2*k+1]=x1;
  }

  const int smemBytes = SM_FLOATS * 4;   // 124,288 B
  cudaFuncSetAttribute(k_fused, cudaFuncAttributeMaxDynamicSharedMemorySize, smemBytes);

  k_topk  <<<NROWS,256>>>(probas, mask);
  k_sample<<<512,  256>>>(mask, bvocab, keys);
  k_hw    <<<64,   256>>>(h_d, mask, W1);
  k_fused <<<128,  256, smemBytes>>>(emb, mask, W1, b1);
  k_carry <<<1,   1024>>>(out + (size_t)out_size - NBv);
  k_out   <<<NROWS,256>>>(probas, mask, out);
}

// round 9
// speedup vs baseline: 3.8869x; 1.0419x over previous
#include <cuda_runtime.h>
#include <math.h>

#define NBv 16
#define NLv 64
#define Vv  16384
#define Dv  256
#define TK  16
#define NIT 8
#define NROWS (NBv*NLv)   // 1024

// ---------------- scratch (static device memory; no allocs) ----------------
__device__ float  g_logits[NROWS][TK];
__device__ int    g_topidx[NROWS][TK];
__device__ int    g_map[NROWS];
__device__ float  g_rowsum[NROWS];
__device__ int    g_samples[NIT][NROWS];
__device__ int    g_gidx[NIT][NROWS];
__device__ float  g_HW[NBv][NLv*Dv];
__device__ float  g_scores[NIT][NBv];
__device__ int    g_best[NROWS];

// ---------------- threefry2x32 (JAX 20-round), host+device ----------------
__host__ __device__ inline void tf2x32(unsigned k0, unsigned k1, unsigned& x0, unsigned& x1){
  unsigned ks2 = k0 ^ k1 ^ 0x1BD11BDAu;
#define ROTL32(x,d) (((x)<<(d))|((x)>>(32-(d))))
#define TFRND(r) { x0 += x1; x1 = ROTL32(x1,(r)); x1 ^= x0; }
  x0 += k0; x1 += k1;
  TFRND(13) TFRND(15) TFRND(26) TFRND(6)
  x0 += k1; x1 += ks2 + 1u;
  TFRND(17) TFRND(29) TFRND(16) TFRND(24)
  x0 += ks2; x1 += k0 + 2u;
  TFRND(13) TFRND(15) TFRND(26) TFRND(6)
  x0 += k0; x1 += k1 + 3u;
  TFRND(17) TFRND(29) TFRND(16) TFRND(24)
  x0 += k1; x1 += ks2 + 4u;
  TFRND(13) TFRND(15) TFRND(26) TFRND(6)
  x0 += ks2; x1 += k0 + 5u;
#undef TFRND
#undef ROTL32
}

struct Keys { unsigned a[2*NIT]; };

// ---------------- f32x2 helpers ----------------
__device__ __forceinline__ unsigned long long pk2(float x, float y){
  unsigned long long r; asm("mov.b64 %0, {%1, %2};" : "=l"(r) : "f"(x), "f"(y)); return r;
}
__device__ __forceinline__ unsigned long long fma2(unsigned long long a, unsigned long long b, unsigned long long c){
  unsigned long long d; asm("fma.rn.f32x2 %0, %1, %2, %3;" : "=l"(d) : "l"(a), "l"(b), "l"(c)); return d;
}
__device__ __forceinline__ float2 upk(unsigned long long v){
  float2 f; asm("mov.b64 {%0, %1}, %2;" : "=f"(f.x), "=f"(f.y) : "l"(v)); return f;
}

// ---------------- kernel 1: per-row top-16 + argmax + logits + rowsum --------
__global__ __launch_bounds__(256) void k_topk(const float* __restrict__ probas,
                                              const int* __restrict__ mask){
  int row = blockIdx.x;
  const float4* p4 = (const float4*)(probas + (size_t)row * Vv);
  int t = threadIdx.x;
  int lane = t & 31, warp = t >> 5;

  __shared__ unsigned long long cand[512];
  __shared__ int scnt;
  __shared__ float ssum[8];
  __shared__ unsigned long long sw8[8][TK];
  if (t==0) scnt=0;
  __syncthreads();

  const unsigned TH = __float_as_uint(0.997f);
  float sum = 0.f;
#pragma unroll 4
  for (int i=0;i<16;i++){
    int v4 = i*256 + t;
    float4 x = __ldg(&p4[v4]);
    sum += (x.x + x.y) + (x.z + x.w);
    float xs[4] = {x.x, x.y, x.z, x.w};
#pragma unroll
    for (int q=0;q<4;q++){
      unsigned fb = __float_as_uint(xs[q]);
      if (fb > TH){
        int pos = atomicAdd(&scnt, 1);
        if (pos < 512)
          cand[pos] = ((unsigned long long)fb<<32) | (unsigned)(~(v4*4+q));
      }
    }
  }
#pragma unroll
  for (int d=16; d>0; d>>=1) sum += __shfl_xor_sync(0xffffffffu, sum, d);
  if (lane==0) ssum[warp]=sum;
  __syncthreads();
  if (t==0){
    float s2=0.f;
#pragma unroll
    for (int i=0;i<8;i++) s2+=ssum[i];
    g_rowsum[row]=s2;
  }
  int cnt = scnt;

  if (cnt>=16 && cnt<=512){
    if (warp==0){
      int jn = (cnt+31)>>5;
      unsigned long long lm=0ull;
      for (int j=0;j<jn;j++){
        int s=lane+32*j;
        unsigned long long k2 = (s<cnt)? cand[s] : 0ull;
        if (k2>lm) lm=k2;
      }
      unsigned long long mine=0ull;
      for (int r=0;r<TK;r++){
        unsigned long long bk=lm;
#pragma unroll
        for (int d=16;d>0;d>>=1){
          unsigned long long o=__shfl_xor_sync(0xffffffffu,bk,d);
          if (o>bk) bk=o;
        }
        if (lm==bk){
          lm=0ull;
          for (int j=0;j<jn;j++){
            int s=lane+32*j;
            unsigned long long k2=(s<cnt)? cand[s] : 0ull;
            if (k2==bk) cand[s]=0ull;
            else if (k2>lm) lm=k2;
          }
        }
        if (lane==r) mine=bk;
      }
      if (lane<TK){
        int idx = (int)(~(unsigned)mine);
        float val = __uint_as_float((unsigned)(mine>>32));
        g_topidx[row][lane]=idx;
        g_logits[row][lane] = mask[row] ? logf(val) : 0.0f;
        if (lane==0) g_map[row]=idx;
      }
    }
    return;
  }

  // -------- exact slow fallback (never taken on expected data) --------
  unsigned long long v[TK];
#pragma unroll
  for (int i=0;i<TK;i++) v[i]=0ull;
#pragma unroll 2
  for (int i=0;i<16;i++){
    int v4 = i*256 + t;
    float4 x = __ldg(&p4[v4]);
    float xs[4] = {x.x, x.y, x.z, x.w};
#pragma unroll
    for (int q=0;q<4;q++){
      unsigned fb = __float_as_uint(xs[q]);
      unsigned long long carry = ((unsigned long long)fb<<32) | (unsigned)(~(v4*4+q));
#pragma unroll
      for (int u=0;u<TK;u++){
        unsigned long long hi = (v[u]>carry)? v[u]:carry;
        unsigned long long lo = (v[u]>carry)? carry:v[u];
        v[u]=hi; carry=lo;
      }
    }
  }
  unsigned long long mine = 0ull;
  for (int r=0;r<TK;r++){
    unsigned long long bh = v[0]; int bl = lane;
#pragma unroll
    for (int d=16; d>0; d>>=1){
      unsigned long long oh = __shfl_xor_sync(0xffffffffu, bh, d);
      int ol = __shfl_xor_sync(0xffffffffu, bl, d);
      if (oh > bh){ bh=oh; bl=ol; }
    }
    if (lane==bl){
#pragma unroll
      for (int u=0;u<TK-1;u++) v[u]=v[u+1];
      v[TK-1]=0ull;
    }
    if (lane==r) mine = bh;
  }
  if (lane<TK) sw8[warp][lane] = mine;
  __syncthreads();
  if (warp==0){
    unsigned long long c[4];
    int wsrc = lane>>2, base=(lane&3)*4;
#pragma unroll
    for (int j=0;j<4;j++) c[j]=sw8[wsrc][base+j];
    unsigned long long res = 0ull;
    for (int r=0;r<TK;r++){
      unsigned long long bh=c[0]; int bl=lane;
#pragma unroll
      for (int d=16; d>0; d>>=1){
        unsigned long long oh = __shfl_xor_sync(0xffffffffu, bh, d);
        int ol = __shfl_xor_sync(0xffffffffu, bl, d);
        if (oh > bh){ bh=oh; bl=ol; }
      }
      if (lane==bl){ c[0]=c[1]; c[1]=c[2]; c[2]=c[3]; c[3]=0ull; }
      if (lane==r) res = bh;
    }
    if (lane<TK){
      int idx = (int)(~(unsigned)res);
      float val = __uint_as_float((unsigned)(res>>32));
      g_topidx[row][lane]=idx;
      g_logits[row][lane] = mask[row] ? logf(val) : 0.0f;
      if (lane==0) g_map[row]=idx;
    }
  }
}

// ---------------- kernel 2: gumbel-categorical sampling ----------------
__global__ __launch_bounds__(256) void k_sample(const int* __restrict__ mask,
                                                 const int* __restrict__ bvocab, Keys keys){
  int flat = blockIdx.x*256 + threadIdx.x;   // 0..131071
  int j   = flat & 15;
  int row = (flat>>4) & (NROWS-1);
  int k   = flat >> 14;
  unsigned k0=keys.a[2*k], k1=keys.a[2*k+1];
  unsigned x0=0u, x1=(unsigned)(row*TK + j);
  tf2x32(k0,k1,x0,x1);
  unsigned bits = x0 ^ x1;
  unsigned ub = (bits>>9) | 0x3f800000u;
  float f = __uint_as_float(ub) - 1.0f;
  float u = (f>0.f)? f : 1.17549435e-38f;
  float s = -logf(-logf(u)) + g_logits[row][j];
  int arg = j;
#pragma unroll
  for (int w=1; w<16; w<<=1){
    float os = __shfl_xor_sync(0xffffffffu, s, w);
    int   oa = __shfl_xor_sync(0xffffffffu, arg, w);
    if (os>s || (os==s && oa<arg)){ s=os; arg=oa; }
  }
  if (j==0){
    int smp = g_topidx[row][arg];
    int ll = row&63;
    bool oh = mask[row] && (ll==63 || mask[row+1]==0);
    if (oh) smp = g_map[row];
    g_samples[k][row]=smp;
    g_gidx[k][row]=bvocab[smp];
  }
}

// ---------------- kernel 3: HW[b] = (h_d*mask) @ W1[256:512] ----------------
__global__ __launch_bounds__(256) void k_hw(const float* __restrict__ h_d,
                                            const int* __restrict__ mask,
                                            const float* __restrict__ W1){
  int blk = blockIdx.x; int b = blk>>2; int cc = (blk&3)*64;
  int t = threadIdx.x; int ty=t>>4, tx=t&15;
  __shared__ float As[32][65];
  __shared__ float Bs[32][64];
  __shared__ float mf[64];
  if (t<64) mf[t] = (float)mask[b*64+t];
  __syncthreads();
  float acc[4][4];
#pragma unroll
  for (int i=0;i<4;i++)
#pragma unroll
    for (int j=0;j<4;j++) acc[i][j]=0.f;
  for (int k0=0;k0<Dv;k0+=32){
#pragma unroll
    for (int i=0;i<8;i++){
      int e=t+i*256; int r=e>>5, kk=e&31;
      As[kk][r] = h_d[((size_t)b*64+r)*Dv + k0+kk] * mf[r];
    }
#pragma unroll
    for (int i=0;i<8;i++){
      int e=t+i*256; int kk=e>>6, c=e&63;
      Bs[kk][c] = W1[(size_t)(Dv + k0+kk)*Dv + cc + c];
    }
    __syncthreads();
#pragma unroll
    for (int kk=0;kk<32;kk++){
      float a0=As[kk][ty],a1=As[kk][ty+16],a2=As[kk][ty+32],a3=As[kk][ty+48];
      float w0=Bs[kk][tx],w1=Bs[kk][tx+16],w2=Bs[kk][tx+32],w3=Bs[kk][tx+48];
      acc[0][0]+=a0*w0; acc[0][1]+=a0*w1; acc[0][2]+=a0*w2; acc[0][3]+=a0*w3;
      acc[1][0]+=a1*w0; acc[1][1]+=a1*w1; acc[1][2]+=a1*w2; acc[1][3]+=a1*w3;
      acc[2][0]+=a2*w0; acc[2][1]+=a2*w1; acc[2][2]+=a2*w2; acc[2][3]+=a2*w3;
      acc[3][0]+=a3*w0; acc[3][1]+=a3*w1; acc[3][2]+=a3*w2; acc[3][3]+=a3*w3;
    }
    __syncthreads();
  }
#pragma unroll
  for (int ri=0;ri<4;ri++)
#pragma unroll
    for (int ci=0;ci<4;ci++)
      g_HW[b][(ty+16*ri)*Dv + cc + tx+16*ci] = acc[ri][ci];
}

// ---------------- kernel 4: FUSED  NE = relu(E@W1a + HW + b1) -> Gram -> det
// One block per task (grid=128). All smem accesses vectorized to LDS.128;
// NE A-operand loads are warp-uniform (broadcast, 1 crossbar phase).
// Layout (floats): NEs 64x260 | AsT 64x36 | Bs 32x260 | M 64x65
#define NE_STRIDE 260
#define OFF_AS  16640
#define AS_STRIDE 36
#define OFF_BS  (OFF_AS + 64*AS_STRIDE)       // 18944
#define BS_STRIDE 260
#define OFF_M   (OFF_BS + 32*BS_STRIDE)       // 27264
#define SM_FLOATS (OFF_M + 64*65)             // 31424
#define M_S(r,c)  sm[OFF_M + (r)*65 + (c)]

__global__ __launch_bounds__(256,1) void k_fused(const float* __restrict__ emb,
                                                 const int* __restrict__ mask,
                                                 const float* __restrict__ W1,
                                                 const float* __restrict__ b1){
  extern __shared__ float sm[];
  int task=blockIdx.x;                 // k*16+b
  int kit=task>>4, b=task&15;
  int t=threadIdx.x; int warp=t>>5, lane=t&31;
  __shared__ int gid[64]; __shared__ float mf[64]; __shared__ int vld[64];
  __shared__ float fct[64];
  __shared__ int sn;
  __shared__ double sdet;
  if (t<64){ gid[t]=g_gidx[kit][b*64+t]; int m=mask[b*64+t]; mf[t]=(float)m; vld[t]=m; }
  if (t==0){ sdet=1.0; sn=0; }
  __syncthreads();

  // ---- phase 1: NE = relu(E@W1[0:256] + HW + b1), 64x256 into smem ----
  unsigned long long acc[8][4];
#pragma unroll
  for (int i=0;i<8;i++)
#pragma unroll
    for (int j=0;j<4;j++) acc[i][j]=0ull;

  float4 pa[2]; float4 pb[8];
#pragma unroll
  for (int i=0;i<2;i++){ int e=t+i*256; int r=e>>3, kq=e&7;
    float4 v=*(const float4*)&emb[(size_t)gid[r]*Dv + 4*kq];
    float m=mf[r]; v.x*=m; v.y*=m; v.z*=m; v.w*=m; pa[i]=v; }
#pragma unroll
  for (int i=0;i<8;i++){ int e=t+i*256; int kk=e>>6, cq=e&63;
    pb[i]=*(const float4*)&W1[(size_t)kk*Dv + 4*cq]; }

  for (int tile=0;tile<8;tile++){
#pragma unroll
    for (int i=0;i<2;i++){ int e=t+i*256; int r=e>>3, kq=e&7;
      *(float4*)&sm[OFF_AS + r*AS_STRIDE + 4*kq] = pa[i]; }
#pragma unroll
    for (int i=0;i<8;i++){ int e=t+i*256; int kk=e>>6, cq=e&63;
      *(float4*)&sm[OFF_BS + kk*BS_STRIDE + 4*cq] = pb[i]; }
    __syncthreads();
    if (tile<7){
      int k0=32*(tile+1);
#pragma unroll
      for (int i=0;i<2;i++){ int e=t+i*256; int r=e>>3, kq=e&7;
        float4 v=*(const float4*)&emb[(size_t)gid[r]*Dv + k0 + 4*kq];
        float m=mf[r]; v.x*=m; v.y*=m; v.z*=m; v.w*=m; pa[i]=v; }
#pragma unroll
      for (int i=0;i<8;i++){ int e=t+i*256; int kk=e>>6, cq=e&63;
        pb[i]=*(const float4*)&W1[(size_t)(k0+kk)*Dv + 4*cq]; }
    }
#pragma unroll
    for (int kq=0;kq<8;kq++){
      float4 aq[8];
#pragma unroll
      for (int ri=0;ri<8;ri++)
        aq[ri]=*(const float4*)&sm[OFF_AS + (warp+8*ri)*AS_STRIDE + 4*kq];
#pragma unroll
      for (int s=0;s<4;s++){
        float4 w0=*(const float4*)&sm[OFF_BS + (4*kq+s)*BS_STRIDE + 4*lane];
        float4 w1=*(const float4*)&sm[OFF_BS + (4*kq+s)*BS_STRIDE + 4*lane+128];
        unsigned long long wp0=pk2(w0.x,w0.y), wp1=pk2(w0.z,w0.w);
        unsigned long long wp2=pk2(w1.x,w1.y), wp3=pk2(w1.z,w1.w);
#pragma unroll
        for (int ri=0;ri<8;ri++){
          float av = (s==0)?aq[ri].x:(s==1)?aq[ri].y:(s==2)?aq[ri].z:aq[ri].w;
          unsigned long long ap=pk2(av,av);
          acc[ri][0]=fma2(ap,wp0,acc[ri][0]);
          acc[ri][1]=fma2(ap,wp1,acc[ri][1]);
          acc[ri][2]=fma2(ap,wp2,acc[ri][2]);
          acc[ri][3]=fma2(ap,wp3,acc[ri][3]);
        }
      }
    }
    __syncthreads();
  }
#pragma unroll
  for (int ri=0;ri<8;ri++){
    int r=warp+8*ri;
#pragma unroll
    for (int p=0;p<2;p++){
      float2 v0=upk(acc[ri][2*p]), v1=upk(acc[ri][2*p+1]);
      int c=4*lane+128*p;
      float4 hw=*(const float4*)&g_HW[b][r*Dv+c];
      float4 bb=*(const float4*)&b1[c];
      float4 o;
      o.x=fmaxf(v0.x+hw.x+bb.x,0.f);
      o.y=fmaxf(v0.y+hw.y+bb.y,0.f);
      o.z=fmaxf(v1.x+hw.z+bb.z,0.f);
      o.w=fmaxf(v1.y+hw.w+bb.w,0.f);
      *(float4*)&sm[r*NE_STRIDE+c]=o;
    }
  }
  __syncthreads();

  // ---- phase 2: Gram via float4-over-k loads + f32x2 FMA ----
  {
    int ti=t>>4, tj=t&15;
    unsigned long long g2[4][4];
#pragma unroll
    for (int i=0;i<4;i++)
#pragma unroll
      for (int j=0;j<4;j++) g2[i][j]=0ull;
#pragma unroll 4
    for (int q=0;q<64;q++){
      unsigned long long alo[4],ahi[4],clo[4],chi[4];
#pragma unroll
      for (int m=0;m<4;m++){
        float4 a=*(const float4*)&sm[(ti+16*m)*NE_STRIDE+4*q];
        float4 c=*(const float4*)&sm[(tj+16*m)*NE_STRIDE+4*q];
        alo[m]=pk2(a.x,a.y); ahi[m]=pk2(a.z,a.w);
        clo[m]=pk2(c.x,c.y); chi[m]=pk2(c.z,c.w);
      }
#pragma unroll
      for (int i=0;i<4;i++)
#pragma unroll
        for (int j=0;j<4;j++){
          g2[i][j]=fma2(alo[i],clo[j],g2[i][j]);
          g2[i][j]=fma2(ahi[i],chi[j],g2[i][j]);
        }
    }
    __syncthreads();
#pragma unroll
    for (int i=0;i<4;i++)
#pragma unroll
      for (int j=0;j<4;j++){
        int r=ti+16*i, c=tj+16*j;
        float2 gv=upk(g2[i][j]);
        float v=gv.x+gv.y;
        if (!(vld[r] && vld[c])) v=(r==c)?1.f:0.f;
        M_S(r,c)=v;
      }
    __syncthreads();
  }

  // ---- phase 3: no-pivot LU det over leading sLen block ----
  if (t<64 && vld[t] && (t==63 || !vld[t+1])) sn=t+1;
  __syncthreads();
  int sl = sn;
  for (int i=0;i<sl;i++){
    float piv = M_S(i,i);
    if (t<64 && t>i) fct[t]=M_S(t,i)/piv;
    if (t==0) sdet *= (double)piv;
    __syncthreads();
    int tr=t>>6, tc=t&63;
    if (tc>i){
      float mi=M_S(i,tc);
      for (int r=i+1+tr; r<sl; r+=4)
        M_S(r,tc) -= fct[r]*mi;
    }
    __syncthreads();
  }
  if (t==0) g_scores[kit][b] = (float)sdet;
}

// ---------------- kernel 6: scan-carry (improved/count/stopped) ----------------
__global__ __launch_bounds__(1024) void k_carry(float* __restrict__ out_scores){
  int t=threadIdx.x;
  __shared__ float ms[NBv];
  __shared__ int sbest[NROWS];
  __shared__ int imp[NBv];
  __shared__ int s_ost, s_count, s_stop;
  if (t<NBv) ms[t]=-INFINITY;
  sbest[t]=g_map[t];
  if (t==0){s_count=0;s_stop=0;s_ost=0;}
  __syncthreads();
  for (int k=0;k<NIT;k++){
    if (t<NBv) imp[t] = (g_scores[k][t] > ms[t])?1:0;
    __syncthreads();
    if (t==0){
      int a=0; for (int bb=0;bb<NBv;bb++) a|=imp[bb];
      s_ost = s_stop;
      s_count = a?0:(s_count+1);
      if ((!a) && s_count>=2) s_stop=1;
    }
    __syncthreads();
    if (t<NBv && imp[t] && !s_ost) ms[t]=g_scores[k][t];
    if (imp[t>>6] && !s_ost) sbest[t]=g_samples[k][t];
    __syncthreads();
  }
  g_best[t]=sbest[t];
  if (t<NBv) out_scores[t]=ms[t];
}

// ---------------- kernel 7: diverse_proba scatter-renormalize (1 pass) ------
__global__ __launch_bounds__(256) void k_out(const float* __restrict__ probas,
                                             const int* __restrict__ mask,
                                             float* __restrict__ out){
  int row=blockIdx.x;
  const float4* p4 = (const float4*)(probas + (size_t)row*Vv);
  float4* o4 = (float4*)(out + (size_t)row*Vv);
  int t=threadIdx.x;
  int bv = g_best[row];
  int bv4 = bv>>2, bvl = bv&3;
  float nm;
  if (mask[row]){
    float pbst = __ldg(&probas[(size_t)row*Vv + bv]);
    nm = 0.2f*g_rowsum[row] + 0.6f*pbst;
  } else nm = 1e-10f;
  float inv = 1.0f/nm;
#pragma unroll 4
  for (int i=0;i<16;i++){
    int v4=i*256+t;
    float4 x = __ldg(&p4[v4]);
    float w0=(v4==bv4&&bvl==0)?0.8f:0.2f, w1=(v4==bv4&&bvl==1)?0.8f:0.2f;
    float w2=(v4==bv4&&bvl==2)?0.8f:0.2f, w3=(v4==bv4&&bvl==3)?0.8f:0.2f;
    float4 y; y.x=x.x*w0*inv; y.y=x.y*w1*inv; y.z=x.z*w2*inv; y.w=x.w*w3*inv;
    o4[v4]=y;
  }
}

// ---------------- launch ----------------
extern "C" void kernel_launch(void* const* d_in, const int* in_sizes, int n_in,
                              void* d_out, int out_size){
  const float* probas = (const float*)d_in[0];
  const float* h_d    = (const float*)d_in[1];
  const int*   mask   = (const int*)d_in[2];
  const int*   bvocab = (const int*)d_in[3];
  const float* emb    = (const float*)d_in[4];
  const float* W1     = (const float*)d_in[5];
  const float* b1     = (const float*)d_in[6];
  float* out = (float*)d_out;
  (void)in_sizes; (void)n_in;

  Keys keys;
  for (int k=0;k<NIT;k++){
    unsigned x0=0u, x1=(unsigned)k;
    tf2x32(0u,42u,x0,x1);
    keys.a[2*k]=x0; keys.a[2*k+1]=x1;
  }

  const int smemBytes = SM_FLOATS * 4;   // 125,696 B
  cudaFuncSetAttribute(k_fused, cudaFuncAttributeMaxDynamicSharedMemorySize, smemBytes);

  k_topk  <<<NROWS,256>>>(probas, mask);
  k_sample<<<512,  256>>>(mask, bvocab, keys);
  k_hw    <<<64,   256>>>(h_d, mask, W1);
  k_fused <<<128,  256, smemBytes>>>(emb, mask, W1, b1);
  k_carry <<<1,   1024>>>(out + (size_t)out_size - NBv);
  k_out   <<<NROWS,256>>>(probas, mask, out);
}

// round 10
// speedup vs baseline: 3.9740x; 1.0224x over previous
#include <cuda_runtime.h>
#include <math.h>

#define NBv 16
#define NLv 64
#define Vv  16384
#define Dv  256
#define TK  16
#define NIT 8
#define NROWS (NBv*NLv)   // 1024

// ---------------- scratch (static device memory; no allocs) ----------------
__device__ float  g_logits[NROWS][TK];
__device__ int    g_topidx[NROWS][TK];
__device__ int    g_map[NROWS];
__device__ float  g_rowsum[NROWS];
__device__ int    g_samples[NIT][NROWS];
__device__ int    g_gidx[NIT][NROWS];
__device__ float  g_HW[NBv][NLv*Dv];
__device__ float  g_scores[NIT][NBv];
__device__ int    g_best[NROWS];

// ---------------- threefry2x32 (JAX 20-round), host+device ----------------
__host__ __device__ inline void tf2x32(unsigned k0, unsigned k1, unsigned& x0, unsigned& x1){
  unsigned ks2 = k0 ^ k1 ^ 0x1BD11BDAu;
#define ROTL32(x,d) (((x)<<(d))|((x)>>(32-(d))))
#define TFRND(r) { x0 += x1; x1 = ROTL32(x1,(r)); x1 ^= x0; }
  x0 += k0; x1 += k1;
  TFRND(13) TFRND(15) TFRND(26) TFRND(6)
  x0 += k1; x1 += ks2 + 1u;
  TFRND(17) TFRND(29) TFRND(16) TFRND(24)
  x0 += ks2; x1 += k0 + 2u;
  TFRND(13) TFRND(15) TFRND(26) TFRND(6)
  x0 += k0; x1 += k1 + 3u;
  TFRND(17) TFRND(29) TFRND(16) TFRND(24)
  x0 += k1; x1 += ks2 + 4u;
  TFRND(13) TFRND(15) TFRND(26) TFRND(6)
  x0 += ks2; x1 += k0 + 5u;
#undef TFRND
#undef ROTL32
}

struct Keys { unsigned a[2*NIT]; };

// ---------------- f32x2 helpers ----------------
__device__ __forceinline__ unsigned long long pk2(float x, float y){
  unsigned long long r; asm("mov.b64 %0, {%1, %2};" : "=l"(r) : "f"(x), "f"(y)); return r;
}
__device__ __forceinline__ unsigned long long fma2(unsigned long long a, unsigned long long b, unsigned long long c){
  unsigned long long d; asm("fma.rn.f32x2 %0, %1, %2, %3;" : "=l"(d) : "l"(a), "l"(b), "l"(c)); return d;
}
__device__ __forceinline__ float2 upk(unsigned long long v){
  float2 f; asm("mov.b64 {%0, %1}, %2;" : "=f"(f.x), "=f"(f.y) : "l"(v)); return f;
}

// ---------------- kernel 1: per-row top-16 + argmax + logits + rowsum --------
__global__ __launch_bounds__(256) void k_topk(const float* __restrict__ probas,
                                              const int* __restrict__ mask){
  int row = blockIdx.x;
  const float4* p4 = (const float4*)(probas + (size_t)row * Vv);
  int t = threadIdx.x;
  int lane = t & 31, warp = t >> 5;

  __shared__ unsigned long long cand[512];
  __shared__ int scnt;
  __shared__ float ssum[8];
  __shared__ unsigned long long sw8[8][TK];
  if (t==0) scnt=0;
  __syncthreads();

  const unsigned TH = __float_as_uint(0.997f);
  float sum = 0.f;
#pragma unroll 4
  for (int i=0;i<16;i++){
    int v4 = i*256 + t;
    float4 x = __ldg(&p4[v4]);
    sum += (x.x + x.y) + (x.z + x.w);
    float xs[4] = {x.x, x.y, x.z, x.w};
#pragma unroll
    for (int q=0;q<4;q++){
      unsigned fb = __float_as_uint(xs[q]);
      if (fb > TH){
        int pos = atomicAdd(&scnt, 1);
        if (pos < 512)
          cand[pos] = ((unsigned long long)fb<<32) | (unsigned)(~(v4*4+q));
      }
    }
  }
#pragma unroll
  for (int d=16; d>0; d>>=1) sum += __shfl_xor_sync(0xffffffffu, sum, d);
  if (lane==0) ssum[warp]=sum;
  __syncthreads();
  if (t==0){
    float s2=0.f;
#pragma unroll
    for (int i=0;i<8;i++) s2+=ssum[i];
    g_rowsum[row]=s2;
  }
  int cnt = scnt;

  if (cnt>=16 && cnt<=512){
    if (warp==0){
      int jn = (cnt+31)>>5;
      unsigned long long lm=0ull;
      for (int j=0;j<jn;j++){
        int s=lane+32*j;
        unsigned long long k2 = (s<cnt)? cand[s] : 0ull;
        if (k2>lm) lm=k2;
      }
      unsigned long long mine=0ull;
      for (int r=0;r<TK;r++){
        unsigned long long bk=lm;
#pragma unroll
        for (int d=16;d>0;d>>=1){
          unsigned long long o=__shfl_xor_sync(0xffffffffu,bk,d);
          if (o>bk) bk=o;
        }
        if (lm==bk){
          lm=0ull;
          for (int j=0;j<jn;j++){
            int s=lane+32*j;
            unsigned long long k2=(s<cnt)? cand[s] : 0ull;
            if (k2==bk) cand[s]=0ull;
            else if (k2>lm) lm=k2;
          }
        }
        if (lane==r) mine=bk;
      }
      if (lane<TK){
        int idx = (int)(~(unsigned)mine);
        float val = __uint_as_float((unsigned)(mine>>32));
        g_topidx[row][lane]=idx;
        g_logits[row][lane] = mask[row] ? logf(val) : 0.0f;
        if (lane==0) g_map[row]=idx;
      }
    }
    return;
  }

  // -------- exact slow fallback (never taken on expected data) --------
  unsigned long long v[TK];
#pragma unroll
  for (int i=0;i<TK;i++) v[i]=0ull;
#pragma unroll 2
  for (int i=0;i<16;i++){
    int v4 = i*256 + t;
    float4 x = __ldg(&p4[v4]);
    float xs[4] = {x.x, x.y, x.z, x.w};
#pragma unroll
    for (int q=0;q<4;q++){
      unsigned fb = __float_as_uint(xs[q]);
      unsigned long long carry = ((unsigned long long)fb<<32) | (unsigned)(~(v4*4+q));
#pragma unroll
      for (int u=0;u<TK;u++){
        unsigned long long hi = (v[u]>carry)? v[u]:carry;
        unsigned long long lo = (v[u]>carry)? carry:v[u];
        v[u]=hi; carry=lo;
      }
    }
  }
  unsigned long long mine = 0ull;
  for (int r=0;r<TK;r++){
    unsigned long long bh = v[0]; int bl = lane;
#pragma unroll
    for (int d=16; d>0; d>>=1){
      unsigned long long oh = __shfl_xor_sync(0xffffffffu, bh, d);
      int ol = __shfl_xor_sync(0xffffffffu, bl, d);
      if (oh > bh){ bh=oh; bl=ol; }
    }
    if (lane==bl){
#pragma unroll
      for (int u=0;u<TK-1;u++) v[u]=v[u+1];
      v[TK-1]=0ull;
    }
    if (lane==r) mine = bh;
  }
  if (lane<TK) sw8[warp][lane] = mine;
  __syncthreads();
  if (warp==0){
    unsigned long long c[4];
    int wsrc = lane>>2, base=(lane&3)*4;
#pragma unroll
    for (int j=0;j<4;j++) c[j]=sw8[wsrc][base+j];
    unsigned long long res = 0ull;
    for (int r=0;r<TK;r++){
      unsigned long long bh=c[0]; int bl=lane;
#pragma unroll
      for (int d=16; d>0; d>>=1){
        unsigned long long oh = __shfl_xor_sync(0xffffffffu, bh, d);
        int ol = __shfl_xor_sync(0xffffffffu, bl, d);
        if (oh > bh){ bh=oh; bl=ol; }
      }
      if (lane==bl){ c[0]=c[1]; c[1]=c[2]; c[2]=c[3]; c[3]=0ull; }
      if (lane==r) res = bh;
    }
    if (lane<TK){
      int idx = (int)(~(unsigned)res);
      float val = __uint_as_float((unsigned)(res>>32));
      g_topidx[row][lane]=idx;
      g_logits[row][lane] = mask[row] ? logf(val) : 0.0f;
      if (lane==0) g_map[row]=idx;
    }
  }
}

// ---------------- kernel 2: gumbel-categorical sampling ----------------
__global__ __launch_bounds__(256) void k_sample(const int* __restrict__ mask,
                                                 const int* __restrict__ bvocab, Keys keys){
  int flat = blockIdx.x*256 + threadIdx.x;   // 0..131071
  int j   = flat & 15;
  int row = (flat>>4) & (NROWS-1);
  int k   = flat >> 14;
  unsigned k0=keys.a[2*k], k1=keys.a[2*k+1];
  unsigned x0=0u, x1=(unsigned)(row*TK + j);
  tf2x32(k0,k1,x0,x1);
  unsigned bits = x0 ^ x1;
  unsigned ub = (bits>>9) | 0x3f800000u;
  float f = __uint_as_float(ub) - 1.0f;
  float u = (f>0.f)? f : 1.17549435e-38f;
  float s = -logf(-logf(u)) + g_logits[row][j];
  int arg = j;
#pragma unroll
  for (int w=1; w<16; w<<=1){
    float os = __shfl_xor_sync(0xffffffffu, s, w);
    int   oa = __shfl_xor_sync(0xffffffffu, arg, w);
    if (os>s || (os==s && oa<arg)){ s=os; arg=oa; }
  }
  if (j==0){
    int smp = g_topidx[row][arg];
    int ll = row&63;
    bool oh = mask[row] && (ll==63 || mask[row+1]==0);
    if (oh) smp = g_map[row];
    g_samples[k][row]=smp;
    g_gidx[k][row]=bvocab[smp];
  }
}

// ---------------- kernel 3: HW[b] = (h_d*mask) @ W1[256:512] ----------------
__global__ __launch_bounds__(256) void k_hw(const float* __restrict__ h_d,
                                            const int* __restrict__ mask,
                                            const float* __restrict__ W1){
  int blk = blockIdx.x; int b = blk>>2; int cc = (blk&3)*64;
  int t = threadIdx.x; int ty=t>>4, tx=t&15;
  __shared__ float As[32][65];
  __shared__ float Bs[32][64];
  __shared__ float mf[64];
  if (t<64) mf[t] = (float)mask[b*64+t];
  __syncthreads();
  float acc[4][4];
#pragma unroll
  for (int i=0;i<4;i++)
#pragma unroll
    for (int j=0;j<4;j++) acc[i][j]=0.f;
  for (int k0=0;k0<Dv;k0+=32){
#pragma unroll
    for (int i=0;i<8;i++){
      int e=t+i*256; int r=e>>5, kk=e&31;
      As[kk][r] = h_d[((size_t)b*64+r)*Dv + k0+kk] * mf[r];
    }
#pragma unroll
    for (int i=0;i<8;i++){
      int e=t+i*256; int kk=e>>6, c=e&63;
      Bs[kk][c] = W1[(size_t)(Dv + k0+kk)*Dv + cc + c];
    }
    __syncthreads();
#pragma unroll
    for (int kk=0;kk<32;kk++){
      float a0=As[kk][ty],a1=As[kk][ty+16],a2=As[kk][ty+32],a3=As[kk][ty+48];
      float w0=Bs[kk][tx],w1=Bs[kk][tx+16],w2=Bs[kk][tx+32],w3=Bs[kk][tx+48];
      acc[0][0]+=a0*w0; acc[0][1]+=a0*w1; acc[0][2]+=a0*w2; acc[0][3]+=a0*w3;
      acc[1][0]+=a1*w0; acc[1][1]+=a1*w1; acc[1][2]+=a1*w2; acc[1][3]+=a1*w3;
      acc[2][0]+=a2*w0; acc[2][1]+=a2*w1; acc[2][2]+=a2*w2; acc[2][3]+=a2*w3;
      acc[3][0]+=a3*w0; acc[3][1]+=a3*w1; acc[3][2]+=a3*w2; acc[3][3]+=a3*w3;
    }
    __syncthreads();
  }
#pragma unroll
  for (int ri=0;ri<4;ri++)
#pragma unroll
    for (int ci=0;ci<4;ci++)
      g_HW[b][(ty+16*ri)*Dv + cc + tx+16*ci] = acc[ri][ci];
}

// ---------------- kernel 4: FUSED  NE = relu(E@W1a + HW + b1) -> Gram -> det
// 512 threads/block (4 warps/SMSP for latency hiding). grid=128.
// Layout (floats): NEs 64x260 | AsT 64x36 | Bs 32x260 | M 64x65 | M2 64x65
#define NE_STRIDE 260
#define OFF_AS  16640
#define AS_STRIDE 36
#define OFF_BS  (OFF_AS + 64*AS_STRIDE)       // 18944
#define BS_STRIDE 260
#define OFF_M   (OFF_BS + 32*BS_STRIDE)       // 27264
#define OFF_M2  (OFF_M + 64*65)               // 31424
#define SM_FLOATS (OFF_M2 + 64*65)            // 35584
#define M_S(r,c)   sm[OFF_M  + (r)*65 + (c)]
#define M2_S(r,c)  sm[OFF_M2 + (r)*65 + (c)]

__global__ __launch_bounds__(512,1) void k_fused(const float* __restrict__ emb,
                                                 const int* __restrict__ mask,
                                                 const float* __restrict__ W1,
                                                 const float* __restrict__ b1){
  extern __shared__ float sm[];
  int task=blockIdx.x;                 // k*16+b
  int kit=task>>4, b=task&15;
  int t=threadIdx.x; int warp=t>>5, lane=t&31;
  __shared__ int gid[64]; __shared__ float mf[64]; __shared__ int vld[64];
  __shared__ float fct[64];
  __shared__ int sn;
  __shared__ double sdet;
  if (t<64){ gid[t]=g_gidx[kit][b*64+t]; int m=mask[b*64+t]; mf[t]=(float)m; vld[t]=m; }
  if (t==0){ sdet=1.0; sn=0; }
  __syncthreads();

  // ---- phase 1: NE = relu(E@W1[0:256] + HW + b1), 64x256 into smem ----
  unsigned long long acc[4][4];
#pragma unroll
  for (int i=0;i<4;i++)
#pragma unroll
    for (int j=0;j<4;j++) acc[i][j]=0ull;

  float4 pa; float4 pb[4];
  { int r=t>>3, kq=t&7;
    float4 v=*(const float4*)&emb[(size_t)gid[r]*Dv + 4*kq];
    float m=mf[r]; v.x*=m; v.y*=m; v.z*=m; v.w*=m; pa=v; }
#pragma unroll
  for (int i=0;i<4;i++){ int e=t+i*512; int kk=e>>6, cq=e&63;
    pb[i]=*(const float4*)&W1[(size_t)kk*Dv + 4*cq]; }

  for (int tile=0;tile<8;tile++){
    { int r=t>>3, kq=t&7;
      *(float4*)&sm[OFF_AS + r*AS_STRIDE + 4*kq] = pa; }
#pragma unroll
    for (int i=0;i<4;i++){ int e=t+i*512; int kk=e>>6, cq=e&63;
      *(float4*)&sm[OFF_BS + kk*BS_STRIDE + 4*cq] = pb[i]; }
    __syncthreads();
    if (tile<7){
      int k0=32*(tile+1);
      { int r=t>>3, kq=t&7;
        float4 v=*(const float4*)&emb[(size_t)gid[r]*Dv + k0 + 4*kq];
        float m=mf[r]; v.x*=m; v.y*=m; v.z*=m; v.w*=m; pa=v; }
#pragma unroll
      for (int i=0;i<4;i++){ int e=t+i*512; int kk=e>>6, cq=e&63;
        pb[i]=*(const float4*)&W1[(size_t)(k0+kk)*Dv + 4*cq]; }
    }
#pragma unroll
    for (int kq=0;kq<8;kq++){
      float4 aq[4];
#pragma unroll
      for (int ri=0;ri<4;ri++)
        aq[ri]=*(const float4*)&sm[OFF_AS + (warp+16*ri)*AS_STRIDE + 4*kq];
#pragma unroll
      for (int s=0;s<4;s++){
        float4 w0=*(const float4*)&sm[OFF_BS + (4*kq+s)*BS_STRIDE + 4*lane];
        float4 w1=*(const float4*)&sm[OFF_BS + (4*kq+s)*BS_STRIDE + 4*lane+128];
        unsigned long long wp0=pk2(w0.x,w0.y), wp1=pk2(w0.z,w0.w);
        unsigned long long wp2=pk2(w1.x,w1.y), wp3=pk2(w1.z,w1.w);
#pragma unroll
        for (int ri=0;ri<4;ri++){
          float av = (s==0)?aq[ri].x:(s==1)?aq[ri].y:(s==2)?aq[ri].z:aq[ri].w;
          unsigned long long ap=pk2(av,av);
          acc[ri][0]=fma2(ap,wp0,acc[ri][0]);
          acc[ri][1]=fma2(ap,wp1,acc[ri][1]);
          acc[ri][2]=fma2(ap,wp2,acc[ri][2]);
          acc[ri][3]=fma2(ap,wp3,acc[ri][3]);
        }
      }
    }
    __syncthreads();
  }
#pragma unroll
  for (int ri=0;ri<4;ri++){
    int r=warp+16*ri;
#pragma unroll
    for (int p=0;p<2;p++){
      float2 v0=upk(acc[ri][2*p]), v1=upk(acc[ri][2*p+1]);
      int c=4*lane+128*p;
      float4 hw=*(const float4*)&g_HW[b][r*Dv+c];
      float4 bb=*(const float4*)&b1[c];
      float4 o;
      o.x=fmaxf(v0.x+hw.x+bb.x,0.f);
      o.y=fmaxf(v0.y+hw.y+bb.y,0.f);
      o.z=fmaxf(v1.x+hw.z+bb.z,0.f);
      o.w=fmaxf(v1.y+hw.w+bb.w,0.f);
      *(float4*)&sm[r*NE_STRIDE+c]=o;
    }
  }
  __syncthreads();

  // ---- phase 2: Gram, k-split over thread halves, then merged+masked ----
  {
    int half = t>>8;            // 0: k<128, 1: k>=128
    int tt = t&255;
    int ti=tt>>4, tj=tt&15;
    unsigned long long g2[4][4];
#pragma unroll
    for (int i=0;i<4;i++)
#pragma unroll
      for (int j=0;j<4;j++) g2[i][j]=0ull;
    int q0 = 32*half;
#pragma unroll 4
    for (int qq=0;qq<32;qq++){
      int q = q0+qq;
      unsigned long long alo[4],ahi[4],clo[4],chi[4];
#pragma unroll
      for (int m=0;m<4;m++){
        float4 a=*(const float4*)&sm[(ti+16*m)*NE_STRIDE+4*q];
        float4 c=*(const float4*)&sm[(tj+16*m)*NE_STRIDE+4*q];
        alo[m]=pk2(a.x,a.y); ahi[m]=pk2(a.z,a.w);
        clo[m]=pk2(c.x,c.y); chi[m]=pk2(c.z,c.w);
      }
#pragma unroll
      for (int i=0;i<4;i++)
#pragma unroll
        for (int j=0;j<4;j++){
          g2[i][j]=fma2(alo[i],clo[j],g2[i][j]);
          g2[i][j]=fma2(ahi[i],chi[j],g2[i][j]);
        }
    }
#pragma unroll
    for (int i=0;i<4;i++)
#pragma unroll
      for (int j=0;j<4;j++){
        int r=ti+16*i, c=tj+16*j;
        float2 gv=upk(g2[i][j]);
        float v=gv.x+gv.y;
        if (half==0) M_S(r,c)=v; else M2_S(r,c)=v;
      }
    __syncthreads();
    if (t<256){
#pragma unroll
      for (int i=0;i<4;i++)
#pragma unroll
        for (int j=0;j<4;j++){
          int r=ti+16*i, c=tj+16*j;
          float v = M_S(r,c) + M2_S(r,c);
          if (!(vld[r] && vld[c])) v=(r==c)?1.f:0.f;
          M_S(r,c)=v;
        }
    }
    __syncthreads();
  }

  // ---- phase 3: no-pivot LU det over leading sLen block ----
  if (t<64 && vld[t] && (t==63 || !vld[t+1])) sn=t+1;
  __syncthreads();
  int sl = sn;
  for (int i=0;i<sl;i++){
    float piv = M_S(i,i);
    if (t<64 && t>i) fct[t]=M_S(t,i)/piv;
    if (t==0) sdet *= (double)piv;
    __syncthreads();
    int tr=t>>6, tc=t&63;
    if (tc>i){
      float mi=M_S(i,tc);
      for (int r=i+1+tr; r<sl; r+=8)
        M_S(r,tc) -= fct[r]*mi;
    }
    __syncthreads();
  }
  if (t==0) g_scores[kit][b] = (float)sdet;
}

// ---------------- kernel 6: scan-carry (improved/count/stopped) ----------------
__global__ __launch_bounds__(1024) void k_carry(float* __restrict__ out_scores){
  int t=threadIdx.x;
  __shared__ float ms[NBv];
  __shared__ int sbest[NROWS];
  __shared__ int imp[NBv];
  __shared__ int s_ost, s_count, s_stop;
  if (t<NBv) ms[t]=-INFINITY;
  sbest[t]=g_map[t];
  if (t==0){s_count=0;s_stop=0;s_ost=0;}
  __syncthreads();
  for (int k=0;k<NIT;k++){
    if (t<NBv) imp[t] = (g_scores[k][t] > ms[t])?1:0;
    __syncthreads();
    if (t==0){
      int a=0; for (int bb=0;bb<NBv;bb++) a|=imp[bb];
      s_ost = s_stop;
      s_count = a?0:(s_count+1);
      if ((!a) && s_count>=2) s_stop=1;
    }
    __syncthreads();
    if (t<NBv && imp[t] && !s_ost) ms[t]=g_scores[k][t];
    if (imp[t>>6] && !s_ost) sbest[t]=g_samples[k][t];
    __syncthreads();
  }
  g_best[t]=sbest[t];
  if (t<NBv) out_scores[t]=ms[t];
}

// ---------------- kernel 7: diverse_proba scatter-renormalize (1 pass) ------
__global__ __launch_bounds__(256) void k_out(const float* __restrict__ probas,
                                             const int* __restrict__ mask,
                                             float* __restrict__ out){
  int row=blockIdx.x;
  const float4* p4 = (const float4*)(probas + (size_t)row*Vv);
  float4* o4 = (float4*)(out + (size_t)row*Vv);
  int t=threadIdx.x;
  int bv = g_best[row];
  int bv4 = bv>>2, bvl = bv&3;
  float nm;
  if (mask[row]){
    float pbst = __ldg(&probas[(size_t)row*Vv + bv]);
    nm = 0.2f*g_rowsum[row] + 0.6f*pbst;
  } else nm = 1e-10f;
  float inv = 1.0f/nm;
#pragma unroll 4
  for (int i=0;i<16;i++){
    int v4=i*256+t;
    float4 x = __ldg(&p4[v4]);
    float w0=(v4==bv4&&bvl==0)?0.8f:0.2f, w1=(v4==bv4&&bvl==1)?0.8f:0.2f;
    float w2=(v4==bv4&&bvl==2)?0.8f:0.2f, w3=(v4==bv4&&bvl==3)?0.8f:0.2f;
    float4 y; y.x=x.x*w0*inv; y.y=x.y*w1*inv; y.z=x.z*w2*inv; y.w=x.w*w3*inv;
    o4[v4]=y;
  }
}

// ---------------- launch ----------------
extern "C" void kernel_launch(void* const* d_in, const int* in_sizes, int n_in,
                              void* d_out, int out_size){
  const float* probas = (const float*)d_in[0];
  const float* h_d    = (const float*)d_in[1];
  const int*   mask   = (const int*)d_in[2];
  const int*   bvocab = (const int*)d_in[3];
  const float* emb    = (const float*)d_in[4];
  const float* W1     = (const float*)d_in[5];
  const float* b1     = (const float*)d_in[6];
  float* out = (float*)d_out;
  (void)in_sizes; (void)n_in;

  Keys keys;
  for (int k=0;k<NIT;k++){
    unsigned x0=0u, x1=(unsigned)k;
    tf2x32(0u,42u,x0,x1);
    keys.a[2*k]=x0; keys.a[2*k+1]=x1;
  }

  const int smemBytes = SM_FLOATS * 4;   // 142,336 B
  cudaFuncSetAttribute(k_fused, cudaFuncAttributeMaxDynamicSharedMemorySize, smemBytes);

  k_topk  <<<NROWS,256>>>(probas, mask);
  k_sample<<<512,  256>>>(mask, bvocab, keys);
  k_hw    <<<64,   256>>>(h_d, mask, W1);
  k_fused <<<128,  512, smemBytes>>>(emb, mask, W1, b1);
  k_carry <<<1,   1024>>>(out + (size_t)out_size - NBv);
  k_out   <<<NROWS,256>>>(probas, mask, out);
}